// round 1
// baseline (speedup 1.0000x reference)
#include <cuda_runtime.h>
#include <cuda_bf16.h>

// Problem shape (fixed per reference): B=8, S=2048, D=1024
#define BATCH 8
#define SEQ   2048
#define DIM   1024

// ---------------- scratch (device globals: allocation-free) ----------------
__device__ float g_q[(long long)BATCH * SEQ * DIM];           // 64 MB
__device__ float g_k[(long long)BATCH * SEQ * DIM];           // 64 MB
__device__ float g_v[(long long)BATCH * SEQ * DIM];           // 64 MB
__device__ float g_sc[(long long)BATCH * SEQ * SEQ];          // 128 MB
__device__ float g_o[(long long)BATCH * SEQ * DIM];           // 64 MB

// ---------------- tiled fp32 GEMM params ----------------
#define BM 128
#define BN 128
#define BK 8
#define TM 8
#define TN 8
// threads per block = (BM/TM)*(BN/TN) = 256

// C[m,n] = sum_k A[m,k] * B[k,n]  (+bias[n] if bias != nullptr)
// A: [M,K] row-major (lda=K), B: [K,N] row-major (ldb=N), C: [M,N] (ldc=N)
// blockIdx.z batches via sA/sB/sC element strides.
__global__ __launch_bounds__(256) void sgemm_nn(
    const float* __restrict__ A, const float* __restrict__ B,
    const float* __restrict__ bias, float* __restrict__ C,
    int M, int N, int K, long long sA, long long sB, long long sC)
{
    A += (long long)blockIdx.z * sA;
    B += (long long)blockIdx.z * sB;
    C += (long long)blockIdx.z * sC;

    __shared__ float As[BK][BM];
    __shared__ float Bs[BK][BN];

    const int tid  = threadIdx.x;
    const int brow = blockIdx.y * BM;
    const int bcol = blockIdx.x * BN;

    // A tile loader: 128 rows x 8 k, float4 along k
    const int arow = tid >> 1;          // 0..127
    const int acol = (tid & 1) << 2;    // 0 or 4
    // B tile loader: 8 k-rows x 128 cols, float4 along n
    const int bkr  = tid >> 5;          // 0..7
    const int bnc  = (tid & 31) << 2;   // 0..124

    const int ty = tid >> 4;            // 0..15 (row group)
    const int tx = tid & 15;            // 0..15 (col group)

    float acc[TM][TN];
    #pragma unroll
    for (int i = 0; i < TM; i++)
        #pragma unroll
        for (int j = 0; j < TN; j++) acc[i][j] = 0.f;

    for (int k0 = 0; k0 < K; k0 += BK) {
        float4 av = *reinterpret_cast<const float4*>(
            &A[(long long)(brow + arow) * K + k0 + acol]);
        As[acol + 0][arow] = av.x;
        As[acol + 1][arow] = av.y;
        As[acol + 2][arow] = av.z;
        As[acol + 3][arow] = av.w;

        float4 bv = *reinterpret_cast<const float4*>(
            &B[(long long)(k0 + bkr) * N + bcol + bnc]);
        *reinterpret_cast<float4*>(&Bs[bkr][bnc]) = bv;
        __syncthreads();

        #pragma unroll
        for (int kk = 0; kk < BK; kk++) {
            float4 a0 = *reinterpret_cast<const float4*>(&As[kk][ty * TM]);
            float4 a1 = *reinterpret_cast<const float4*>(&As[kk][ty * TM + 4]);
            float4 b0 = *reinterpret_cast<const float4*>(&Bs[kk][tx * TN]);
            float4 b1 = *reinterpret_cast<const float4*>(&Bs[kk][tx * TN + 4]);
            float ar[TM] = {a0.x, a0.y, a0.z, a0.w, a1.x, a1.y, a1.z, a1.w};
            float br[TN] = {b0.x, b0.y, b0.z, b0.w, b1.x, b1.y, b1.z, b1.w};
            #pragma unroll
            for (int i = 0; i < TM; i++)
                #pragma unroll
                for (int j = 0; j < TN; j++)
                    acc[i][j] += ar[i] * br[j];
        }
        __syncthreads();
    }

    #pragma unroll
    for (int i = 0; i < TM; i++) {
        long long r = brow + ty * TM + i;
        #pragma unroll
        for (int j = 0; j < TN; j += 4) {
            int c = bcol + tx * TN + j;
            float4 v = make_float4(acc[i][j], acc[i][j+1], acc[i][j+2], acc[i][j+3]);
            if (bias) {
                v.x += bias[c + 0]; v.y += bias[c + 1];
                v.z += bias[c + 2]; v.w += bias[c + 3];
            }
            *reinterpret_cast<float4*>(&C[r * N + c]) = v;
        }
    }
}

// C[m,n] = sum_d A[m,d] * B[n,d]   (NT: both K-major; scores = Q @ K^T)
// A: [M,K] (lda=K), B: [N,K] (ldb=K), C: [M,N] (ldc=N)
__global__ __launch_bounds__(256) void sgemm_nt(
    const float* __restrict__ A, const float* __restrict__ B,
    float* __restrict__ C,
    int M, int N, int K, long long sA, long long sB, long long sC)
{
    A += (long long)blockIdx.z * sA;
    B += (long long)blockIdx.z * sB;
    C += (long long)blockIdx.z * sC;

    __shared__ float As[BK][BM];
    __shared__ float Bs[BK][BN];

    const int tid  = threadIdx.x;
    const int brow = blockIdx.y * BM;
    const int bcol = blockIdx.x * BN;

    const int arow = tid >> 1;          // 0..127
    const int acol = (tid & 1) << 2;    // 0 or 4

    const int ty = tid >> 4;
    const int tx = tid & 15;

    float acc[TM][TN];
    #pragma unroll
    for (int i = 0; i < TM; i++)
        #pragma unroll
        for (int j = 0; j < TN; j++) acc[i][j] = 0.f;

    for (int k0 = 0; k0 < K; k0 += BK) {
        float4 av = *reinterpret_cast<const float4*>(
            &A[(long long)(brow + arow) * K + k0 + acol]);
        As[acol + 0][arow] = av.x;
        As[acol + 1][arow] = av.y;
        As[acol + 2][arow] = av.z;
        As[acol + 3][arow] = av.w;

        float4 bv = *reinterpret_cast<const float4*>(
            &B[(long long)(bcol + arow) * K + k0 + acol]);
        Bs[acol + 0][arow] = bv.x;
        Bs[acol + 1][arow] = bv.y;
        Bs[acol + 2][arow] = bv.z;
        Bs[acol + 3][arow] = bv.w;
        __syncthreads();

        #pragma unroll
        for (int kk = 0; kk < BK; kk++) {
            float4 a0 = *reinterpret_cast<const float4*>(&As[kk][ty * TM]);
            float4 a1 = *reinterpret_cast<const float4*>(&As[kk][ty * TM + 4]);
            float4 b0 = *reinterpret_cast<const float4*>(&Bs[kk][tx * TN]);
            float4 b1 = *reinterpret_cast<const float4*>(&Bs[kk][tx * TN + 4]);
            float ar[TM] = {a0.x, a0.y, a0.z, a0.w, a1.x, a1.y, a1.z, a1.w};
            float br[TN] = {b0.x, b0.y, b0.z, b0.w, b1.x, b1.y, b1.z, b1.w};
            #pragma unroll
            for (int i = 0; i < TM; i++)
                #pragma unroll
                for (int j = 0; j < TN; j++)
                    acc[i][j] += ar[i] * br[j];
        }
        __syncthreads();
    }

    #pragma unroll
    for (int i = 0; i < TM; i++) {
        long long r = brow + ty * TM + i;
        #pragma unroll
        for (int j = 0; j < TN; j += 4) {
            int c = bcol + tx * TN + j;
            float4 v = make_float4(acc[i][j], acc[i][j+1], acc[i][j+2], acc[i][j+3]);
            *reinterpret_cast<float4*>(&C[r * N + c]) = v;
        }
    }
}

// Row-wise softmax over SEQ=2048 elements; one 256-thread block per row.
__global__ __launch_bounds__(256) void softmax_rows(float* __restrict__ Sc)
{
    const int n = SEQ;
    float* p = Sc + (long long)blockIdx.x * n;
    const int tid = threadIdx.x, lane = tid & 31, w = tid >> 5;

    __shared__ float rmax[8];
    __shared__ float rsum[8];

    float vals[8];
    float m = -3.0e38f;
    #pragma unroll
    for (int i = 0; i < 8; i++) {
        vals[i] = p[tid + i * 256];
        m = fmaxf(m, vals[i]);
    }
    #pragma unroll
    for (int o = 16; o; o >>= 1) m = fmaxf(m, __shfl_xor_sync(0xffffffffu, m, o));
    if (lane == 0) rmax[w] = m;
    __syncthreads();
    m = rmax[0];
    #pragma unroll
    for (int i = 1; i < 8; i++) m = fmaxf(m, rmax[i]);

    float s = 0.f;
    #pragma unroll
    for (int i = 0; i < 8; i++) {
        vals[i] = __expf(vals[i] - m);
        s += vals[i];
    }
    #pragma unroll
    for (int o = 16; o; o >>= 1) s += __shfl_xor_sync(0xffffffffu, s, o);
    if (lane == 0) rsum[w] = s;
    __syncthreads();
    s = rsum[0];
    #pragma unroll
    for (int i = 1; i < 8; i++) s += rsum[i];

    float inv = 1.0f / s;
    #pragma unroll
    for (int i = 0; i < 8; i++) p[tid + i * 256] = vals[i] * inv;
}

// out[row] = dot(O[row, :], Wo) + bo ; one warp per row.
__global__ __launch_bounds__(256) void out_proj(
    const float* __restrict__ O, const float* __restrict__ Wo,
    const float* __restrict__ bo, float* __restrict__ out)
{
    const int warp = (blockIdx.x * blockDim.x + threadIdx.x) >> 5;
    const int lane = threadIdx.x & 31;
    if (warp >= BATCH * SEQ) return;
    const float* row = O + (long long)warp * DIM;
    float s = 0.f;
    #pragma unroll 8
    for (int i = lane; i < DIM; i += 32) s += row[i] * Wo[i];
    #pragma unroll
    for (int o = 16; o; o >>= 1) s += __shfl_xor_sync(0xffffffffu, s, o);
    if (lane == 0) out[warp] = s + bo[0];
}

extern "C" void kernel_launch(void* const* d_in, const int* in_sizes, int n_in,
                              void* d_out, int out_size)
{
    const float* x  = (const float*)d_in[0];
    const float* Wq = (const float*)d_in[1];
    const float* bq = (const float*)d_in[2];
    const float* Wk = (const float*)d_in[3];
    const float* bk = (const float*)d_in[4];
    const float* Wv = (const float*)d_in[5];
    const float* bv = (const float*)d_in[6];
    const float* Wo = (const float*)d_in[7];
    const float* bo = (const float*)d_in[8];
    float* out = (float*)d_out;

    float *q, *k, *v, *sc, *o;
    cudaGetSymbolAddress((void**)&q,  g_q);
    cudaGetSymbolAddress((void**)&k,  g_k);
    cudaGetSymbolAddress((void**)&v,  g_v);
    cudaGetSymbolAddress((void**)&sc, g_sc);
    cudaGetSymbolAddress((void**)&o,  g_o);

    const int M  = BATCH * SEQ;           // 16384
    const long long sQ  = (long long)SEQ * DIM;   // per-batch Q/K/V/O stride
    const long long sSc = (long long)SEQ * SEQ;   // per-batch scores stride

    dim3 blk(256);

    // 1) QKV projections: [16384,1024] x [1024,1024] + bias
    dim3 g1(DIM / BN, M / BM, 1);
    sgemm_nn<<<g1, blk>>>(x, Wq, bq, q, M, DIM, DIM, 0, 0, 0);
    sgemm_nn<<<g1, blk>>>(x, Wk, bk, k, M, DIM, DIM, 0, 0, 0);
    sgemm_nn<<<g1, blk>>>(x, Wv, bv, v, M, DIM, DIM, 0, 0, 0);

    // 2) scores = Q @ K^T per batch: [2048,1024] x [2048,1024]^T
    dim3 g2(SEQ / BN, SEQ / BM, BATCH);
    sgemm_nt<<<g2, blk>>>(q, k, sc, SEQ, SEQ, DIM, sQ, sQ, sSc);

    // 3) softmax over last axis
    softmax_rows<<<BATCH * SEQ, 256>>>(sc);

    // 4) O = attn @ V per batch: [2048,2048] x [2048,1024]
    dim3 g3(DIM / BN, SEQ / BM, BATCH);
    sgemm_nn<<<g3, blk>>>(sc, v, nullptr, o, SEQ, DIM, SEQ, sSc, sQ, sQ);

    // 5) out = O @ Wo + bo : warp per row
    out_proj<<<(BATCH * SEQ * 32) / 256, 256>>>(o, Wo, bo, out);
}

// round 3
// speedup vs baseline: 2.7996x; 2.7996x over previous
#include <cuda_runtime.h>
#include <cuda_bf16.h>
#include <cstdint>

#define BATCH 8
#define SEQ   2048
#define DIM   1024
#define MTOT  (BATCH*SEQ)              // 16384

// ===================== scratch (device globals, allocation-free) =====================
__device__ __align__(16) __nv_bfloat16 g_xhi[(size_t)MTOT*DIM];
__device__ __align__(16) __nv_bfloat16 g_xlo[(size_t)MTOT*DIM];
__device__ __align__(16) __nv_bfloat16 g_wqt_hi[(size_t)DIM*DIM];
__device__ __align__(16) __nv_bfloat16 g_wqt_lo[(size_t)DIM*DIM];
__device__ __align__(16) __nv_bfloat16 g_wkt_hi[(size_t)DIM*DIM];
__device__ __align__(16) __nv_bfloat16 g_wkt_lo[(size_t)DIM*DIM];
__device__ __align__(16) __nv_bfloat16 g_wvt_hi[(size_t)DIM*DIM];
__device__ __align__(16) __nv_bfloat16 g_wvt_lo[(size_t)DIM*DIM];
__device__ __align__(16) __nv_bfloat16 g_qhi[(size_t)MTOT*DIM];
__device__ __align__(16) __nv_bfloat16 g_qlo[(size_t)MTOT*DIM];
__device__ __align__(16) __nv_bfloat16 g_khi[(size_t)MTOT*DIM];
__device__ __align__(16) __nv_bfloat16 g_klo[(size_t)MTOT*DIM];
__device__ __align__(16) float         g_v  [(size_t)MTOT*DIM];
__device__ __align__(16) __nv_bfloat16 g_vthi[(size_t)MTOT*DIM];   // [B][D][S]
__device__ __align__(16) __nv_bfloat16 g_vtlo[(size_t)MTOT*DIM];
__device__ __align__(16) float         g_sc [(size_t)BATCH*SEQ*SEQ];
__device__ __align__(16) __nv_bfloat16 g_ahi[(size_t)BATCH*SEQ*SEQ];
__device__ __align__(16) __nv_bfloat16 g_alo[(size_t)BATCH*SEQ*SEQ];
__device__ __align__(16) float         g_o  [(size_t)MTOT*DIM];

// ===================== helpers =====================
__device__ __forceinline__ uint32_t smem_u32(const void* p) {
    uint32_t a;
    asm("{ .reg .u64 t; cvta.to.shared.u64 t, %1; cvt.u32.u64 %0, t; }" : "=r"(a) : "l"(p));
    return a;
}
__device__ __forceinline__ void cp16(uint32_t saddr, const void* g) {
    asm volatile("cp.async.cg.shared.global [%0], [%1], 16;" :: "r"(saddr), "l"(g));
}
__device__ __forceinline__ void cp_commit() {
    asm volatile("cp.async.commit_group;" ::: "memory");
}
__device__ __forceinline__ void ldsm4(uint32_t* r, uint32_t addr) {
    asm volatile("ldmatrix.sync.aligned.m8n8.x4.shared.b16 {%0,%1,%2,%3}, [%4];"
                 : "=r"(r[0]), "=r"(r[1]), "=r"(r[2]), "=r"(r[3]) : "r"(addr));
}
__device__ __forceinline__ void mma_bf16(float* c, const uint32_t* a, uint32_t b0, uint32_t b1) {
    asm volatile(
        "mma.sync.aligned.m16n8k16.row.col.f32.bf16.bf16.f32 "
        "{%0,%1,%2,%3},{%4,%5,%6,%7},{%8,%9},{%0,%1,%2,%3};"
        : "+f"(c[0]), "+f"(c[1]), "+f"(c[2]), "+f"(c[3])
        : "r"(a[0]), "r"(a[1]), "r"(a[2]), "r"(a[3]), "r"(b0), "r"(b1));
}
__device__ __forceinline__ void split1(float v, __nv_bfloat16& h, __nv_bfloat16& l) {
    h = __float2bfloat16(v);
    l = __float2bfloat16(v - __bfloat162float(h));
}
__device__ __forceinline__ uint32_t swz(uint32_t off) {   // SW128 swizzle
    return off ^ ((off >> 3) & 0x70);
}

// ===================== HMMA GEMM: C[m,n] = sum_k A[m,k]*B[n,k] (x3 split) ==========
// Tile 128(M) x 128(N) x 64(K). 256 threads = 8 warps, warp tile 64x32.
// smem per stage: Ahi 16K | Alo 16K | Bhi 16K | Blo 16K = 64KB; double buffered.
#define STG   65536
#define SEC   16384
#define GEMM_SMEM (2*STG)

__device__ __forceinline__ void prefetch_chunk(
    uint32_t sbase, const __nv_bfloat16* Ahi, const __nv_bfloat16* Alo,
    const __nv_bfloat16* Bhi, const __nv_bfloat16* Blo,
    int rowA0, int rowB0, int ku4, int ru4, int tid)
{
    #pragma unroll
    for (int t = 0; t < 4; t++) {
        int idx = tid + t * 256;            // 0..1023
        int r = idx >> 3, c = idx & 7;
        uint32_t soff = swz((uint32_t)(r * 128 + c * 16));
        size_t gA = (size_t)(rowA0 + r) * ru4 + ku4 + c;
        size_t gB = (size_t)(rowB0 + r) * ru4 + ku4 + c;
        cp16(sbase + 0*SEC + soff, (const uint4*)Ahi + gA);
        cp16(sbase + 1*SEC + soff, (const uint4*)Alo + gA);
        cp16(sbase + 2*SEC + soff, (const uint4*)Bhi + gB);
        cp16(sbase + 3*SEC + soff, (const uint4*)Blo + gB);
    }
}

__global__ __launch_bounds__(256, 1) void gemm_hmma_x3(
    const __nv_bfloat16* __restrict__ Ahi, const __nv_bfloat16* __restrict__ Alo,
    const __nv_bfloat16* __restrict__ Bhi, const __nv_bfloat16* __restrict__ Blo,
    float* __restrict__ Cf, __nv_bfloat16* __restrict__ Chi, __nv_bfloat16* __restrict__ Clo,
    const float* __restrict__ bias,
    int N, int K, long long sA, long long sB, long long sC)
{
    extern __shared__ char smem[];
    const uint32_t sb = smem_u32(smem);
    const int tid  = threadIdx.x;
    const int wid  = tid >> 5;
    const int lane = tid & 31;
    const long long z = blockIdx.z;
    Ahi += z * sA;  Alo += z * sA;
    Bhi += z * sB;  Blo += z * sB;

    const int tileM = blockIdx.y * 128;
    const int tileN = blockIdx.x * 128;
    const int nk    = K >> 6;
    const int ru4   = K >> 3;          // row stride in uint4 (K-major, ld=K)

    const int wm = wid >> 2;           // 0..1
    const int wn = wid & 3;            // 0..3
    const int lrow = lane & 15;
    const int lcolB = (lane >> 4) * 16;  // 0 or 16 bytes

    float acc[4][4][4];
    #pragma unroll
    for (int mi = 0; mi < 4; mi++)
        #pragma unroll
        for (int ni = 0; ni < 4; ni++)
            #pragma unroll
            for (int q = 0; q < 4; q++) acc[mi][ni][q] = 0.f;

    prefetch_chunk(sb, Ahi, Alo, Bhi, Blo, tileM, tileN, 0, ru4, tid);
    cp_commit();

    for (int i = 0; i < nk; i++) {
        const uint32_t stg = sb + (uint32_t)(i & 1) * STG;
        if (i + 1 < nk) {
            prefetch_chunk(sb + (uint32_t)((i + 1) & 1) * STG,
                           Ahi, Alo, Bhi, Blo, tileM, tileN, (i + 1) << 3, ru4, tid);
            cp_commit();
            asm volatile("cp.async.wait_group 1;" ::: "memory");
        } else {
            asm volatile("cp.async.wait_group 0;" ::: "memory");
        }
        __syncthreads();

        #pragma unroll
        for (int ks = 0; ks < 4; ks++) {
            const int kb = ks * 32 + lcolB;
            uint32_t ah[4][4], al[4][4];
            #pragma unroll
            for (int mi = 0; mi < 4; mi++) {
                uint32_t off = swz((uint32_t)((wm * 64 + mi * 16 + lrow) * 128 + kb));
                ldsm4(ah[mi], stg + 0*SEC + off);
                ldsm4(al[mi], stg + 1*SEC + off);
            }
            uint32_t bh[2][4], bl[2][4];
            #pragma unroll
            for (int nj = 0; nj < 2; nj++) {
                uint32_t off = swz((uint32_t)((wn * 32 + nj * 16 + lrow) * 128 + kb));
                ldsm4(bh[nj], stg + 2*SEC + off);
                ldsm4(bl[nj], stg + 3*SEC + off);
            }
            #pragma unroll
            for (int mi = 0; mi < 4; mi++)
                #pragma unroll
                for (int ni = 0; ni < 4; ni++) {
                    const int nj = ni >> 1, lo = ni & 1;
                    mma_bf16(acc[mi][ni], ah[mi], bh[nj][lo], bh[nj][lo + 2]);
                    mma_bf16(acc[mi][ni], ah[mi], bl[nj][lo], bl[nj][lo + 2]);
                    mma_bf16(acc[mi][ni], al[mi], bh[nj][lo], bh[nj][lo + 2]);
                }
        }
        __syncthreads();   // all warps done with stage before it is overwritten
    }

    // ---------------- epilogue ----------------
    const int l4 = lane >> 2;
    const int l2 = (lane & 3) * 2;
    #pragma unroll
    for (int mi = 0; mi < 4; mi++) {
        #pragma unroll
        for (int ni = 0; ni < 4; ni++) {
            const int m = tileM + wm * 64 + mi * 16 + l4;
            const int n = tileN + wn * 32 + ni * 8 + l2;
            float c0 = acc[mi][ni][0], c1 = acc[mi][ni][1];
            float c2 = acc[mi][ni][2], c3 = acc[mi][ni][3];
            if (bias) {
                float b0 = __ldg(&bias[n]), b1 = __ldg(&bias[n + 1]);
                c0 += b0; c1 += b1; c2 += b0; c3 += b1;
            }
            const long long r0 = z * sC + (long long)m * N + n;
            const long long r1 = r0 + (long long)8 * N;
            if (Chi) {
                __nv_bfloat16 h0,l0,h1,l1,h2,l2b,h3,l3;
                split1(c0,h0,l0); split1(c1,h1,l1); split1(c2,h2,l2b); split1(c3,h3,l3);
                uint32_t hw0 = (uint32_t)__bfloat16_as_ushort(h0) | ((uint32_t)__bfloat16_as_ushort(h1) << 16);
                uint32_t lw0 = (uint32_t)__bfloat16_as_ushort(l0) | ((uint32_t)__bfloat16_as_ushort(l1) << 16);
                uint32_t hw1 = (uint32_t)__bfloat16_as_ushort(h2) | ((uint32_t)__bfloat16_as_ushort(h3) << 16);
                uint32_t lw1 = (uint32_t)__bfloat16_as_ushort(l2b)| ((uint32_t)__bfloat16_as_ushort(l3) << 16);
                *(uint32_t*)(Chi + r0) = hw0;  *(uint32_t*)(Clo + r0) = lw0;
                *(uint32_t*)(Chi + r1) = hw1;  *(uint32_t*)(Clo + r1) = lw1;
            } else {
                *(float2*)(Cf + r0) = make_float2(c0, c1);
                *(float2*)(Cf + r1) = make_float2(c2, c3);
            }
        }
    }
}

// ===================== conversion kernels =====================
__global__ __launch_bounds__(256) void split_fp32(
    const float* __restrict__ in, __nv_bfloat16* __restrict__ hi,
    __nv_bfloat16* __restrict__ lo, int n8)
{
    int i = blockIdx.x * 256 + threadIdx.x;
    if (i >= n8) return;
    const float4* p = (const float4*)in;
    float4 a = p[2*i], b = p[2*i+1];
    float vv[8] = {a.x, a.y, a.z, a.w, b.x, b.y, b.z, b.w};
    uint32_t hw[4], lw[4];
    #pragma unroll
    for (int j = 0; j < 4; j++) {
        __nv_bfloat16 h0, l0, h1, l1;
        split1(vv[2*j],   h0, l0);
        split1(vv[2*j+1], h1, l1);
        hw[j] = (uint32_t)__bfloat16_as_ushort(h0) | ((uint32_t)__bfloat16_as_ushort(h1) << 16);
        lw[j] = (uint32_t)__bfloat16_as_ushort(l0) | ((uint32_t)__bfloat16_as_ushort(l1) << 16);
    }
    ((uint4*)hi)[i] = make_uint4(hw[0], hw[1], hw[2], hw[3]);
    ((uint4*)lo)[i] = make_uint4(lw[0], lw[1], lw[2], lw[3]);
}

__global__ __launch_bounds__(256) void wtrans_split(
    const float* __restrict__ W, __nv_bfloat16* __restrict__ Whi,
    __nv_bfloat16* __restrict__ Wlo)
{
    __shared__ float t[32][33];
    const int k0 = blockIdx.x * 32, n0 = blockIdx.y * 32;
    const int tx = threadIdx.x, ty = threadIdx.y;   // block (32,8)
    #pragma unroll
    for (int i = 0; i < 4; i++)
        t[ty + 8*i][tx] = W[(size_t)(k0 + ty + 8*i) * DIM + n0 + tx];
    __syncthreads();
    #pragma unroll
    for (int i = 0; i < 4; i++) {
        float v = t[tx][ty + 8*i];
        __nv_bfloat16 h, l; split1(v, h, l);
        size_t o = (size_t)(n0 + ty + 8*i) * DIM + k0 + tx;
        Whi[o] = h; Wlo[o] = l;
    }
}

__global__ __launch_bounds__(256) void vtrans_split(
    const float* __restrict__ v, __nv_bfloat16* __restrict__ vthi,
    __nv_bfloat16* __restrict__ vtlo)
{
    __shared__ float t[32][33];
    const int s0 = blockIdx.x * 32, d0 = blockIdx.y * 32, b = blockIdx.z;
    const int tx = threadIdx.x, ty = threadIdx.y;
    const float* vb = v + (size_t)b * SEQ * DIM;
    #pragma unroll
    for (int i = 0; i < 4; i++)
        t[ty + 8*i][tx] = vb[(size_t)(s0 + ty + 8*i) * DIM + d0 + tx];
    __syncthreads();
    #pragma unroll
    for (int i = 0; i < 4; i++) {
        float val = t[tx][ty + 8*i];
        __nv_bfloat16 h, l; split1(val, h, l);
        size_t o = ((size_t)b * DIM + d0 + ty + 8*i) * SEQ + s0 + tx;
        vthi[o] = h; vtlo[o] = l;
    }
}

__global__ __launch_bounds__(256) void softmax_split(
    const float* __restrict__ Sc, __nv_bfloat16* __restrict__ Ahi,
    __nv_bfloat16* __restrict__ Alo)
{
    const float* p = Sc + (size_t)blockIdx.x * SEQ;
    const int tid = threadIdx.x, lane = tid & 31, w = tid >> 5;
    __shared__ float rmax[8], rsum[8];

    float vals[8];
    float m = -3.0e38f;
    #pragma unroll
    for (int i = 0; i < 8; i++) { vals[i] = p[tid + i * 256]; m = fmaxf(m, vals[i]); }
    #pragma unroll
    for (int o = 16; o; o >>= 1) m = fmaxf(m, __shfl_xor_sync(0xffffffffu, m, o));
    if (lane == 0) rmax[w] = m;
    __syncthreads();
    m = rmax[0];
    #pragma unroll
    for (int i = 1; i < 8; i++) m = fmaxf(m, rmax[i]);

    float s = 0.f;
    #pragma unroll
    for (int i = 0; i < 8; i++) { vals[i] = __expf(vals[i] - m); s += vals[i]; }
    #pragma unroll
    for (int o = 16; o; o >>= 1) s += __shfl_xor_sync(0xffffffffu, s, o);
    if (lane == 0) rsum[w] = s;
    __syncthreads();
    s = rsum[0];
    #pragma unroll
    for (int i = 1; i < 8; i++) s += rsum[i];

    const float inv = 1.0f / s;
    __nv_bfloat16* ah = Ahi + (size_t)blockIdx.x * SEQ;
    __nv_bfloat16* al = Alo + (size_t)blockIdx.x * SEQ;
    #pragma unroll
    for (int i = 0; i < 8; i++) {
        float v = vals[i] * inv;
        __nv_bfloat16 h, l; split1(v, h, l);
        ah[tid + i * 256] = h; al[tid + i * 256] = l;
    }
}

__global__ __launch_bounds__(256) void out_proj(
    const float* __restrict__ O, const float* __restrict__ Wo,
    const float* __restrict__ bo, float* __restrict__ out)
{
    const int warp = (blockIdx.x * blockDim.x + threadIdx.x) >> 5;
    const int lane = threadIdx.x & 31;
    if (warp >= MTOT) return;
    const float* row = O + (size_t)warp * DIM;
    float s = 0.f;
    #pragma unroll 8
    for (int i = lane; i < DIM; i += 32) s += row[i] * Wo[i];
    #pragma unroll
    for (int o = 16; o; o >>= 1) s += __shfl_xor_sync(0xffffffffu, s, o);
    if (lane == 0) out[warp] = s + bo[0];
}

// ===================== launch =====================
extern "C" void kernel_launch(void* const* d_in, const int* in_sizes, int n_in,
                              void* d_out, int out_size)
{
    const float* x  = (const float*)d_in[0];
    const float* Wq = (const float*)d_in[1];
    const float* bq = (const float*)d_in[2];
    const float* Wk = (const float*)d_in[3];
    const float* bk = (const float*)d_in[4];
    const float* Wv = (const float*)d_in[5];
    const float* bv = (const float*)d_in[6];
    const float* Wo = (const float*)d_in[7];
    const float* bo = (const float*)d_in[8];
    float* out = (float*)d_out;

    __nv_bfloat16 *xhi,*xlo,*wqh,*wql,*wkh,*wkl,*wvh,*wvl,*qhi,*qlo,*khi,*klo,*vthi,*vtlo,*ahi,*alo;
    float *v, *sc, *o;
    cudaGetSymbolAddress((void**)&xhi, g_xhi);   cudaGetSymbolAddress((void**)&xlo, g_xlo);
    cudaGetSymbolAddress((void**)&wqh, g_wqt_hi);cudaGetSymbolAddress((void**)&wql, g_wqt_lo);
    cudaGetSymbolAddress((void**)&wkh, g_wkt_hi);cudaGetSymbolAddress((void**)&wkl, g_wkt_lo);
    cudaGetSymbolAddress((void**)&wvh, g_wvt_hi);cudaGetSymbolAddress((void**)&wvl, g_wvt_lo);
    cudaGetSymbolAddress((void**)&qhi, g_qhi);   cudaGetSymbolAddress((void**)&qlo, g_qlo);
    cudaGetSymbolAddress((void**)&khi, g_khi);   cudaGetSymbolAddress((void**)&klo, g_klo);
    cudaGetSymbolAddress((void**)&v,   g_v);
    cudaGetSymbolAddress((void**)&vthi,g_vthi);  cudaGetSymbolAddress((void**)&vtlo,g_vtlo);
    cudaGetSymbolAddress((void**)&sc,  g_sc);
    cudaGetSymbolAddress((void**)&ahi, g_ahi);   cudaGetSymbolAddress((void**)&alo, g_alo);
    cudaGetSymbolAddress((void**)&o,   g_o);

    cudaFuncSetAttribute(gemm_hmma_x3, cudaFuncAttributeMaxDynamicSharedMemorySize, GEMM_SMEM);

    const long long sQ  = (long long)SEQ * DIM;
    const long long sSc = (long long)SEQ * SEQ;

    // 1) split x into hi/lo bf16
    split_fp32<<<(MTOT*DIM/8 + 255)/256, 256>>>(x, xhi, xlo, MTOT*DIM/8);

    // 2) transpose+split weights: W[k][n] -> Wt[n][k]
    dim3 wb(32, 8), wg(DIM/32, DIM/32);
    wtrans_split<<<wg, wb>>>(Wq, wqh, wql);
    wtrans_split<<<wg, wb>>>(Wk, wkh, wkl);
    wtrans_split<<<wg, wb>>>(Wv, wvh, wvl);

    // 3) projections: q,k -> split bf16 outputs; v -> fp32
    dim3 gp(DIM/128, MTOT/128, 1);
    gemm_hmma_x3<<<gp, 256, GEMM_SMEM>>>(xhi, xlo, wqh, wql, nullptr, qhi, qlo, bq,
                                         DIM, DIM, 0, 0, 0);
    gemm_hmma_x3<<<gp, 256, GEMM_SMEM>>>(xhi, xlo, wkh, wkl, nullptr, khi, klo, bk,
                                         DIM, DIM, 0, 0, 0);
    gemm_hmma_x3<<<gp, 256, GEMM_SMEM>>>(xhi, xlo, wvh, wvl, v, nullptr, nullptr, bv,
                                         DIM, DIM, 0, 0, 0);

    // 4) transpose+split v -> vt [B][D][S]
    dim3 vg(SEQ/32, DIM/32, BATCH);
    vtrans_split<<<vg, wb>>>(v, vthi, vtlo);

    // 5) scores = q @ k^T (per batch, NT)
    dim3 gs(SEQ/128, SEQ/128, BATCH);
    gemm_hmma_x3<<<gs, 256, GEMM_SMEM>>>(qhi, qlo, khi, klo, sc, nullptr, nullptr, nullptr,
                                         SEQ, DIM, sQ, sQ, sSc);

    // 6) softmax + split to bf16 hi/lo
    softmax_split<<<MTOT, 256>>>(sc, ahi, alo);

    // 7) O = attn @ V  (NT against vt)
    dim3 ga(DIM/128, SEQ/128, BATCH);
    gemm_hmma_x3<<<ga, 256, GEMM_SMEM>>>(ahi, alo, vthi, vtlo, o, nullptr, nullptr, nullptr,
                                         DIM, SEQ, sSc, sQ, sQ);

    // 8) final projection
    out_proj<<<(MTOT * 32) / 256, 256>>>(o, Wo, bo, out);
}

// round 4
// speedup vs baseline: 2.8679x; 1.0244x over previous
#include <cuda_runtime.h>
#include <cuda_bf16.h>
#include <cstdint>

#define BATCH 8
#define SEQ   2048
#define DIM   1024
#define MTOT  (BATCH*SEQ)              // 16384

// ===================== scratch (device globals, allocation-free) =====================
__device__ __align__(16) __nv_bfloat16 g_xhi[(size_t)MTOT*DIM];
__device__ __align__(16) __nv_bfloat16 g_xlo[(size_t)MTOT*DIM];
__device__ __align__(16) __nv_bfloat16 g_wqt_hi[(size_t)DIM*DIM];
__device__ __align__(16) __nv_bfloat16 g_wqt_lo[(size_t)DIM*DIM];
__device__ __align__(16) __nv_bfloat16 g_wkt_hi[(size_t)DIM*DIM];
__device__ __align__(16) __nv_bfloat16 g_wkt_lo[(size_t)DIM*DIM];
__device__ __align__(16) __nv_bfloat16 g_wvt_hi[(size_t)DIM*DIM];
__device__ __align__(16) __nv_bfloat16 g_wvt_lo[(size_t)DIM*DIM];
__device__ __align__(16) __nv_bfloat16 g_qhi[(size_t)MTOT*DIM];
__device__ __align__(16) __nv_bfloat16 g_qlo[(size_t)MTOT*DIM];
__device__ __align__(16) __nv_bfloat16 g_khi[(size_t)MTOT*DIM];
__device__ __align__(16) __nv_bfloat16 g_klo[(size_t)MTOT*DIM];
__device__ __align__(16) float         g_v  [(size_t)MTOT*DIM];
__device__ __align__(16) __nv_bfloat16 g_vthi[(size_t)MTOT*DIM];   // [B][D][S]
__device__ __align__(16) __nv_bfloat16 g_vtlo[(size_t)MTOT*DIM];
__device__ __align__(16) float         g_sc [(size_t)BATCH*SEQ*SEQ];
__device__ __align__(16) __nv_bfloat16 g_ahi[(size_t)BATCH*SEQ*SEQ];
__device__ __align__(16) __nv_bfloat16 g_alo[(size_t)BATCH*SEQ*SEQ];
__device__ __align__(16) float         g_o  [(size_t)MTOT*DIM];

// ===================== helpers =====================
__device__ __forceinline__ uint32_t smem_u32(const void* p) {
    uint32_t a;
    asm("{ .reg .u64 t; cvta.to.shared.u64 t, %1; cvt.u32.u64 %0, t; }" : "=r"(a) : "l"(p));
    return a;
}
__device__ __forceinline__ void cp16(uint32_t saddr, const void* g) {
    asm volatile("cp.async.cg.shared.global [%0], [%1], 16;" :: "r"(saddr), "l"(g));
}
__device__ __forceinline__ void cp_commit() {
    asm volatile("cp.async.commit_group;" ::: "memory");
}
__device__ __forceinline__ void ldsm4(uint32_t* r, uint32_t addr) {
    asm volatile("ldmatrix.sync.aligned.m8n8.x4.shared.b16 {%0,%1,%2,%3}, [%4];"
                 : "=r"(r[0]), "=r"(r[1]), "=r"(r[2]), "=r"(r[3]) : "r"(addr));
}
__device__ __forceinline__ void mma_bf16(float* c, const uint32_t* a, uint32_t b0, uint32_t b1) {
    asm volatile(
        "mma.sync.aligned.m16n8k16.row.col.f32.bf16.bf16.f32 "
        "{%0,%1,%2,%3},{%4,%5,%6,%7},{%8,%9},{%0,%1,%2,%3};"
        : "+f"(c[0]), "+f"(c[1]), "+f"(c[2]), "+f"(c[3])
        : "r"(a[0]), "r"(a[1]), "r"(a[2]), "r"(a[3]), "r"(b0), "r"(b1));
}
__device__ __forceinline__ void split1(float v, __nv_bfloat16& h, __nv_bfloat16& l) {
    h = __float2bfloat16(v);
    l = __float2bfloat16(v - __bfloat162float(h));
}
__device__ __forceinline__ uint32_t swz(uint32_t off) {   // SW128 swizzle
    return off ^ ((off >> 3) & 0x70);
}

// ===================== HMMA GEMM: C[m,n] = sum_k A[m,k]*B[n,k] (x3 split) ==========
// Tile 128(M) x 256(N) x 64(K). 256 threads = 8 warps, warp tile 64x64.
// Stage: Ahi 16K | Alo 16K | Bhi 32K | Blo 32K = 96KB; double buffered = 192KB.
#define STG      98304
#define OFF_ALO  16384
#define OFF_BHI  32768
#define OFF_BLO  65536
#define GEMM_SMEM (2*STG)

__device__ __forceinline__ void prefetch_chunk(
    uint32_t sbase, const __nv_bfloat16* Ahi, const __nv_bfloat16* Alo,
    const __nv_bfloat16* Bhi, const __nv_bfloat16* Blo,
    int rowA0, int rowB0, int ku4, int ru4, int tid)
{
    #pragma unroll
    for (int t = 0; t < 4; t++) {                 // A: 128 rows x 8 u4
        int idx = tid + t * 256;
        int r = idx >> 3, c = idx & 7;
        uint32_t soff = swz((uint32_t)(r * 128 + c * 16));
        size_t gA = (size_t)(rowA0 + r) * ru4 + ku4 + c;
        cp16(sbase + soff,           (const uint4*)Ahi + gA);
        cp16(sbase + OFF_ALO + soff, (const uint4*)Alo + gA);
    }
    #pragma unroll
    for (int t = 0; t < 8; t++) {                 // B: 256 rows x 8 u4
        int idx = tid + t * 256;
        int r = idx >> 3, c = idx & 7;
        uint32_t soff = swz((uint32_t)(r * 128 + c * 16));
        size_t gB = (size_t)(rowB0 + r) * ru4 + ku4 + c;
        cp16(sbase + OFF_BHI + soff, (const uint4*)Bhi + gB);
        cp16(sbase + OFF_BLO + soff, (const uint4*)Blo + gB);
    }
}

__global__ __launch_bounds__(256, 1) void gemm_hmma_x3(
    const __nv_bfloat16* __restrict__ Ahi, const __nv_bfloat16* __restrict__ Alo,
    const __nv_bfloat16* __restrict__ Bhi, const __nv_bfloat16* __restrict__ Blo,
    float* __restrict__ Cf, __nv_bfloat16* __restrict__ Chi, __nv_bfloat16* __restrict__ Clo,
    const float* __restrict__ bias,
    int N, int K, long long sA, long long sB, long long sC)
{
    extern __shared__ char smem[];
    const uint32_t sb = smem_u32(smem);
    const int tid  = threadIdx.x;
    const int wid  = tid >> 5;
    const int lane = tid & 31;
    const long long z = blockIdx.z;
    Ahi += z * sA;  Alo += z * sA;
    Bhi += z * sB;  Blo += z * sB;

    const int tileM = blockIdx.y * 128;
    const int tileN = blockIdx.x * 256;
    const int nk    = K >> 6;
    const int ru4   = K >> 3;          // row stride in uint4 (K-major, ld=K)

    const int wm = wid >> 2;           // 0..1 (64-row half)
    const int wn = wid & 3;            // 0..3 (64-col quarter)
    const int lrow  = lane & 15;
    const int lcolB = (lane >> 4) * 16;  // 0 or 16 bytes within 32B k-slab

    float acc[4][8][4];
    #pragma unroll
    for (int mi = 0; mi < 4; mi++)
        #pragma unroll
        for (int ni = 0; ni < 8; ni++)
            #pragma unroll
            for (int q = 0; q < 4; q++) acc[mi][ni][q] = 0.f;

    prefetch_chunk(sb, Ahi, Alo, Bhi, Blo, tileM, tileN, 0, ru4, tid);
    cp_commit();

    for (int i = 0; i < nk; i++) {
        const uint32_t stg = sb + (uint32_t)(i & 1) * STG;
        if (i + 1 < nk) {
            prefetch_chunk(sb + (uint32_t)((i + 1) & 1) * STG,
                           Ahi, Alo, Bhi, Blo, tileM, tileN, (i + 1) << 3, ru4, tid);
            cp_commit();
            asm volatile("cp.async.wait_group 1;" ::: "memory");
        } else {
            asm volatile("cp.async.wait_group 0;" ::: "memory");
        }
        __syncthreads();

        #pragma unroll
        for (int ks = 0; ks < 4; ks++) {
            const int kb = ks * 32 + lcolB;
            uint32_t ah[4][4], al[4][4];
            #pragma unroll
            for (int mi = 0; mi < 4; mi++) {
                uint32_t off = swz((uint32_t)((wm * 64 + mi * 16 + lrow) * 128 + kb));
                ldsm4(ah[mi], stg + off);
                ldsm4(al[mi], stg + OFF_ALO + off);
            }
            #pragma unroll
            for (int nj = 0; nj < 4; nj++) {
                uint32_t off = swz((uint32_t)((wn * 64 + nj * 16 + lrow) * 128 + kb));
                uint32_t bh[4], bl[4];
                ldsm4(bh, stg + OFF_BHI + off);
                ldsm4(bl, stg + OFF_BLO + off);
                #pragma unroll
                for (int mi = 0; mi < 4; mi++) {
                    #pragma unroll
                    for (int lo = 0; lo < 2; lo++) {
                        float* a = acc[mi][nj * 2 + lo];
                        mma_bf16(a, ah[mi], bh[lo], bh[lo + 2]);
                        mma_bf16(a, ah[mi], bl[lo], bl[lo + 2]);
                        mma_bf16(a, al[mi], bh[lo], bh[lo + 2]);
                    }
                }
            }
        }
        __syncthreads();   // all warps done with stage before it is overwritten
    }

    // ---------------- epilogue ----------------
    const int l4 = lane >> 2;
    const int l2 = (lane & 3) * 2;
    #pragma unroll
    for (int mi = 0; mi < 4; mi++) {
        #pragma unroll
        for (int ni = 0; ni < 8; ni++) {
            const int m = tileM + wm * 64 + mi * 16 + l4;
            const int n = tileN + wn * 64 + ni * 8 + l2;
            float c0 = acc[mi][ni][0], c1 = acc[mi][ni][1];
            float c2 = acc[mi][ni][2], c3 = acc[mi][ni][3];
            if (bias) {
                float b0 = __ldg(&bias[n]), b1 = __ldg(&bias[n + 1]);
                c0 += b0; c1 += b1; c2 += b0; c3 += b1;
            }
            const long long r0 = z * sC + (long long)m * N + n;
            const long long r1 = r0 + (long long)8 * N;
            if (Chi) {
                __nv_bfloat16 h0,l0,h1,l1,h2,l2b,h3,l3;
                split1(c0,h0,l0); split1(c1,h1,l1); split1(c2,h2,l2b); split1(c3,h3,l3);
                uint32_t hw0 = (uint32_t)__bfloat16_as_ushort(h0) | ((uint32_t)__bfloat16_as_ushort(h1) << 16);
                uint32_t lw0 = (uint32_t)__bfloat16_as_ushort(l0) | ((uint32_t)__bfloat16_as_ushort(l1) << 16);
                uint32_t hw1 = (uint32_t)__bfloat16_as_ushort(h2) | ((uint32_t)__bfloat16_as_ushort(h3) << 16);
                uint32_t lw1 = (uint32_t)__bfloat16_as_ushort(l2b)| ((uint32_t)__bfloat16_as_ushort(l3) << 16);
                *(uint32_t*)(Chi + r0) = hw0;  *(uint32_t*)(Clo + r0) = lw0;
                *(uint32_t*)(Chi + r1) = hw1;  *(uint32_t*)(Clo + r1) = lw1;
            } else {
                *(float2*)(Cf + r0) = make_float2(c0, c1);
                *(float2*)(Cf + r1) = make_float2(c2, c3);
            }
        }
    }
}

// ===================== conversion kernels =====================
__global__ __launch_bounds__(256) void split_fp32(
    const float* __restrict__ in, __nv_bfloat16* __restrict__ hi,
    __nv_bfloat16* __restrict__ lo, int n8)
{
    int i = blockIdx.x * 256 + threadIdx.x;
    if (i >= n8) return;
    const float4* p = (const float4*)in;
    float4 a = p[2*i], b = p[2*i+1];
    float vv[8] = {a.x, a.y, a.z, a.w, b.x, b.y, b.z, b.w};
    uint32_t hw[4], lw[4];
    #pragma unroll
    for (int j = 0; j < 4; j++) {
        __nv_bfloat16 h0, l0, h1, l1;
        split1(vv[2*j],   h0, l0);
        split1(vv[2*j+1], h1, l1);
        hw[j] = (uint32_t)__bfloat16_as_ushort(h0) | ((uint32_t)__bfloat16_as_ushort(h1) << 16);
        lw[j] = (uint32_t)__bfloat16_as_ushort(l0) | ((uint32_t)__bfloat16_as_ushort(l1) << 16);
    }
    ((uint4*)hi)[i] = make_uint4(hw[0], hw[1], hw[2], hw[3]);
    ((uint4*)lo)[i] = make_uint4(lw[0], lw[1], lw[2], lw[3]);
}

__global__ __launch_bounds__(256) void wtrans_split(
    const float* __restrict__ W, __nv_bfloat16* __restrict__ Whi,
    __nv_bfloat16* __restrict__ Wlo)
{
    __shared__ float t[32][33];
    const int k0 = blockIdx.x * 32, n0 = blockIdx.y * 32;
    const int tx = threadIdx.x, ty = threadIdx.y;   // block (32,8)
    #pragma unroll
    for (int i = 0; i < 4; i++)
        t[ty + 8*i][tx] = W[(size_t)(k0 + ty + 8*i) * DIM + n0 + tx];
    __syncthreads();
    #pragma unroll
    for (int i = 0; i < 4; i++) {
        float v = t[tx][ty + 8*i];
        __nv_bfloat16 h, l; split1(v, h, l);
        size_t o = (size_t)(n0 + ty + 8*i) * DIM + k0 + tx;
        Whi[o] = h; Wlo[o] = l;
    }
}

__global__ __launch_bounds__(256) void vtrans_split(
    const float* __restrict__ v, __nv_bfloat16* __restrict__ vthi,
    __nv_bfloat16* __restrict__ vtlo)
{
    __shared__ float t[32][33];
    const int s0 = blockIdx.x * 32, d0 = blockIdx.y * 32, b = blockIdx.z;
    const int tx = threadIdx.x, ty = threadIdx.y;
    const float* vb = v + (size_t)b * SEQ * DIM;
    #pragma unroll
    for (int i = 0; i < 4; i++)
        t[ty + 8*i][tx] = vb[(size_t)(s0 + ty + 8*i) * DIM + d0 + tx];
    __syncthreads();
    #pragma unroll
    for (int i = 0; i < 4; i++) {
        float val = t[tx][ty + 8*i];
        __nv_bfloat16 h, l; split1(val, h, l);
        size_t o = ((size_t)b * DIM + d0 + ty + 8*i) * SEQ + s0 + tx;
        vthi[o] = h; vtlo[o] = l;
    }
}

__global__ __launch_bounds__(256) void softmax_split(
    const float* __restrict__ Sc, __nv_bfloat16* __restrict__ Ahi,
    __nv_bfloat16* __restrict__ Alo)
{
    const float* p = Sc + (size_t)blockIdx.x * SEQ;
    const int tid = threadIdx.x, lane = tid & 31, w = tid >> 5;
    __shared__ float rmax[8], rsum[8];

    float vals[8];
    float m = -3.0e38f;
    #pragma unroll
    for (int i = 0; i < 8; i++) { vals[i] = p[tid + i * 256]; m = fmaxf(m, vals[i]); }
    #pragma unroll
    for (int o = 16; o; o >>= 1) m = fmaxf(m, __shfl_xor_sync(0xffffffffu, m, o));
    if (lane == 0) rmax[w] = m;
    __syncthreads();
    m = rmax[0];
    #pragma unroll
    for (int i = 1; i < 8; i++) m = fmaxf(m, rmax[i]);

    float s = 0.f;
    #pragma unroll
    for (int i = 0; i < 8; i++) { vals[i] = __expf(vals[i] - m); s += vals[i]; }
    #pragma unroll
    for (int o = 16; o; o >>= 1) s += __shfl_xor_sync(0xffffffffu, s, o);
    if (lane == 0) rsum[w] = s;
    __syncthreads();
    s = rsum[0];
    #pragma unroll
    for (int i = 1; i < 8; i++) s += rsum[i];

    const float inv = 1.0f / s;
    __nv_bfloat16* ah = Ahi + (size_t)blockIdx.x * SEQ;
    __nv_bfloat16* al = Alo + (size_t)blockIdx.x * SEQ;
    #pragma unroll
    for (int i = 0; i < 8; i++) {
        float v = vals[i] * inv;
        __nv_bfloat16 h, l; split1(v, h, l);
        ah[tid + i * 256] = h; al[tid + i * 256] = l;
    }
}

__global__ __launch_bounds__(256) void out_proj(
    const float* __restrict__ O, const float* __restrict__ Wo,
    const float* __restrict__ bo, float* __restrict__ out)
{
    const int warp = (blockIdx.x * blockDim.x + threadIdx.x) >> 5;
    const int lane = threadIdx.x & 31;
    if (warp >= MTOT) return;
    const float* row = O + (size_t)warp * DIM;
    float s = 0.f;
    #pragma unroll 8
    for (int i = lane; i < DIM; i += 32) s += row[i] * Wo[i];
    #pragma unroll
    for (int o = 16; o; o >>= 1) s += __shfl_xor_sync(0xffffffffu, s, o);
    if (lane == 0) out[warp] = s + bo[0];
}

// ===================== launch =====================
extern "C" void kernel_launch(void* const* d_in, const int* in_sizes, int n_in,
                              void* d_out, int out_size)
{
    const float* x  = (const float*)d_in[0];
    const float* Wq = (const float*)d_in[1];
    const float* bq = (const float*)d_in[2];
    const float* Wk = (const float*)d_in[3];
    const float* bk = (const float*)d_in[4];
    const float* Wv = (const float*)d_in[5];
    const float* bv = (const float*)d_in[6];
    const float* Wo = (const float*)d_in[7];
    const float* bo = (const float*)d_in[8];
    float* out = (float*)d_out;

    __nv_bfloat16 *xhi,*xlo,*wqh,*wql,*wkh,*wkl,*wvh,*wvl,*qhi,*qlo,*khi,*klo,*vthi,*vtlo,*ahi,*alo;
    float *v, *sc, *o;
    cudaGetSymbolAddress((void**)&xhi, g_xhi);   cudaGetSymbolAddress((void**)&xlo, g_xlo);
    cudaGetSymbolAddress((void**)&wqh, g_wqt_hi);cudaGetSymbolAddress((void**)&wql, g_wqt_lo);
    cudaGetSymbolAddress((void**)&wkh, g_wkt_hi);cudaGetSymbolAddress((void**)&wkl, g_wkt_lo);
    cudaGetSymbolAddress((void**)&wvh, g_wvt_hi);cudaGetSymbolAddress((void**)&wvl, g_wvt_lo);
    cudaGetSymbolAddress((void**)&qhi, g_qhi);   cudaGetSymbolAddress((void**)&qlo, g_qlo);
    cudaGetSymbolAddress((void**)&khi, g_khi);   cudaGetSymbolAddress((void**)&klo, g_klo);
    cudaGetSymbolAddress((void**)&v,   g_v);
    cudaGetSymbolAddress((void**)&vthi,g_vthi);  cudaGetSymbolAddress((void**)&vtlo,g_vtlo);
    cudaGetSymbolAddress((void**)&sc,  g_sc);
    cudaGetSymbolAddress((void**)&ahi, g_ahi);   cudaGetSymbolAddress((void**)&alo, g_alo);
    cudaGetSymbolAddress((void**)&o,   g_o);

    cudaFuncSetAttribute(gemm_hmma_x3, cudaFuncAttributeMaxDynamicSharedMemorySize, GEMM_SMEM);

    const long long sQ  = (long long)SEQ * DIM;
    const long long sSc = (long long)SEQ * SEQ;

    // 1) split x into hi/lo bf16
    split_fp32<<<(MTOT*DIM/8 + 255)/256, 256>>>(x, xhi, xlo, MTOT*DIM/8);

    // 2) transpose+split weights: W[k][n] -> Wt[n][k]
    dim3 wb(32, 8), wg(DIM/32, DIM/32);
    wtrans_split<<<wg, wb>>>(Wq, wqh, wql);
    wtrans_split<<<wg, wb>>>(Wk, wkh, wkl);
    wtrans_split<<<wg, wb>>>(Wv, wvh, wvl);

    // 3) projections: q,k -> split bf16 outputs; v -> fp32
    dim3 gp(DIM/256, MTOT/128, 1);
    gemm_hmma_x3<<<gp, 256, GEMM_SMEM>>>(xhi, xlo, wqh, wql, nullptr, qhi, qlo, bq,
                                         DIM, DIM, 0, 0, 0);
    gemm_hmma_x3<<<gp, 256, GEMM_SMEM>>>(xhi, xlo, wkh, wkl, nullptr, khi, klo, bk,
                                         DIM, DIM, 0, 0, 0);
    gemm_hmma_x3<<<gp, 256, GEMM_SMEM>>>(xhi, xlo, wvh, wvl, v, nullptr, nullptr, bv,
                                         DIM, DIM, 0, 0, 0);

    // 4) transpose+split v -> vt [B][D][S]
    dim3 vg(SEQ/32, DIM/32, BATCH);
    vtrans_split<<<vg, wb>>>(v, vthi, vtlo);

    // 5) scores = q @ k^T (per batch, NT)
    dim3 gs(SEQ/256, SEQ/128, BATCH);
    gemm_hmma_x3<<<gs, 256, GEMM_SMEM>>>(qhi, qlo, khi, klo, sc, nullptr, nullptr, nullptr,
                                         SEQ, DIM, sQ, sQ, sSc);

    // 6) softmax + split to bf16 hi/lo
    softmax_split<<<MTOT, 256>>>(sc, ahi, alo);

    // 7) O = attn @ V  (NT against vt)
    dim3 ga(DIM/256, SEQ/128, BATCH);
    gemm_hmma_x3<<<ga, 256, GEMM_SMEM>>>(ahi, alo, vthi, vtlo, o, nullptr, nullptr, nullptr,
                                         DIM, SEQ, sSc, sQ, sQ);

    // 8) final projection
    out_proj<<<(MTOT * 32) / 256, 256>>>(o, Wo, bo, out);
}

// round 5
// speedup vs baseline: 4.9737x; 1.7343x over previous
#include <cuda_runtime.h>
#include <cuda_bf16.h>
#include <cstdint>

#define BATCH 8
#define SEQ   2048
#define DIM   1024
#define MTOT  (BATCH*SEQ)              // 16384

// ===================== scratch (device globals, allocation-free) =====================
__device__ __align__(16) __nv_bfloat16 g_xhi[(size_t)MTOT*DIM];
__device__ __align__(16) __nv_bfloat16 g_xlo[(size_t)MTOT*DIM];
__device__ __align__(16) __nv_bfloat16 g_wqt_hi[(size_t)DIM*DIM];
__device__ __align__(16) __nv_bfloat16 g_wqt_lo[(size_t)DIM*DIM];
__device__ __align__(16) __nv_bfloat16 g_wkt_hi[(size_t)DIM*DIM];
__device__ __align__(16) __nv_bfloat16 g_wkt_lo[(size_t)DIM*DIM];
__device__ __align__(16) __nv_bfloat16 g_qhi[(size_t)MTOT*DIM];
__device__ __align__(16) __nv_bfloat16 g_qlo[(size_t)MTOT*DIM];
__device__ __align__(16) __nv_bfloat16 g_khi[(size_t)MTOT*DIM];
__device__ __align__(16) __nv_bfloat16 g_klo[(size_t)MTOT*DIM];
__device__ __align__(16) float         g_sc [(size_t)BATCH*SEQ*SEQ];   // 128 MB
__device__ __align__(16) float         g_wvo[DIM + 1];                 // wvo + bvwo scalar
__device__ __align__(16) float         g_vwo[(size_t)MTOT];            // v @ Wo per token

// ===================== helpers =====================
__device__ __forceinline__ uint32_t smem_u32(const void* p) {
    uint32_t a;
    asm("{ .reg .u64 t; cvta.to.shared.u64 t, %1; cvt.u32.u64 %0, t; }" : "=r"(a) : "l"(p));
    return a;
}
__device__ __forceinline__ void cp16(uint32_t saddr, const void* g) {
    asm volatile("cp.async.cg.shared.global [%0], [%1], 16;" :: "r"(saddr), "l"(g));
}
__device__ __forceinline__ void cp_commit() {
    asm volatile("cp.async.commit_group;" ::: "memory");
}
__device__ __forceinline__ void ldsm4(uint32_t* r, uint32_t addr) {
    asm volatile("ldmatrix.sync.aligned.m8n8.x4.shared.b16 {%0,%1,%2,%3}, [%4];"
                 : "=r"(r[0]), "=r"(r[1]), "=r"(r[2]), "=r"(r[3]) : "r"(addr));
}
__device__ __forceinline__ void mma_bf16(float* c, const uint32_t* a, uint32_t b0, uint32_t b1) {
    asm volatile(
        "mma.sync.aligned.m16n8k16.row.col.f32.bf16.bf16.f32 "
        "{%0,%1,%2,%3},{%4,%5,%6,%7},{%8,%9},{%0,%1,%2,%3};"
        : "+f"(c[0]), "+f"(c[1]), "+f"(c[2]), "+f"(c[3])
        : "r"(a[0]), "r"(a[1]), "r"(a[2]), "r"(a[3]), "r"(b0), "r"(b1));
}
__device__ __forceinline__ void split1(float v, __nv_bfloat16& h, __nv_bfloat16& l) {
    h = __float2bfloat16(v);
    l = __float2bfloat16(v - __bfloat162float(h));
}
__device__ __forceinline__ uint32_t swz(uint32_t off) {   // SW128 swizzle
    return off ^ ((off >> 3) & 0x70);
}

// ===================== HMMA GEMM: C[m,n] = sum_k A[m,k]*B[n,k] (x3 split) ==========
// Tile 128(M) x 256(N) x 64(K). 256 threads = 8 warps, warp tile 64x64.
#define STG      98304
#define OFF_ALO  16384
#define OFF_BHI  32768
#define OFF_BLO  65536
#define GEMM_SMEM (2*STG)

__device__ __forceinline__ void prefetch_chunk(
    uint32_t sbase, const __nv_bfloat16* Ahi, const __nv_bfloat16* Alo,
    const __nv_bfloat16* Bhi, const __nv_bfloat16* Blo,
    int rowA0, int rowB0, int ku4, int ru4, int tid)
{
    #pragma unroll
    for (int t = 0; t < 4; t++) {                 // A: 128 rows x 8 u4
        int idx = tid + t * 256;
        int r = idx >> 3, c = idx & 7;
        uint32_t soff = swz((uint32_t)(r * 128 + c * 16));
        size_t gA = (size_t)(rowA0 + r) * ru4 + ku4 + c;
        cp16(sbase + soff,           (const uint4*)Ahi + gA);
        cp16(sbase + OFF_ALO + soff, (const uint4*)Alo + gA);
    }
    #pragma unroll
    for (int t = 0; t < 8; t++) {                 // B: 256 rows x 8 u4
        int idx = tid + t * 256;
        int r = idx >> 3, c = idx & 7;
        uint32_t soff = swz((uint32_t)(r * 128 + c * 16));
        size_t gB = (size_t)(rowB0 + r) * ru4 + ku4 + c;
        cp16(sbase + OFF_BHI + soff, (const uint4*)Bhi + gB);
        cp16(sbase + OFF_BLO + soff, (const uint4*)Blo + gB);
    }
}

__global__ __launch_bounds__(256, 1) void gemm_hmma_x3(
    const __nv_bfloat16* __restrict__ Ahi, const __nv_bfloat16* __restrict__ Alo,
    const __nv_bfloat16* __restrict__ Bhi, const __nv_bfloat16* __restrict__ Blo,
    float* __restrict__ Cf, __nv_bfloat16* __restrict__ Chi, __nv_bfloat16* __restrict__ Clo,
    const float* __restrict__ bias,
    int N, int K, long long sA, long long sB, long long sC)
{
    extern __shared__ char smem[];
    const uint32_t sb = smem_u32(smem);
    const int tid  = threadIdx.x;
    const int wid  = tid >> 5;
    const int lane = tid & 31;
    const long long z = blockIdx.z;
    Ahi += z * sA;  Alo += z * sA;
    Bhi += z * sB;  Blo += z * sB;

    const int tileM = blockIdx.y * 128;
    const int tileN = blockIdx.x * 256;
    const int nk    = K >> 6;
    const int ru4   = K >> 3;          // row stride in uint4 (K-major, ld=K)

    const int wm = wid >> 2;           // 0..1 (64-row half)
    const int wn = wid & 3;            // 0..3 (64-col quarter)
    const int lrow  = lane & 15;
    const int lcolB = (lane >> 4) * 16;  // 0 or 16 bytes within 32B k-slab

    float acc[4][8][4];
    #pragma unroll
    for (int mi = 0; mi < 4; mi++)
        #pragma unroll
        for (int ni = 0; ni < 8; ni++)
            #pragma unroll
            for (int q = 0; q < 4; q++) acc[mi][ni][q] = 0.f;

    prefetch_chunk(sb, Ahi, Alo, Bhi, Blo, tileM, tileN, 0, ru4, tid);
    cp_commit();

    for (int i = 0; i < nk; i++) {
        const uint32_t stg = sb + (uint32_t)(i & 1) * STG;
        if (i + 1 < nk) {
            prefetch_chunk(sb + (uint32_t)((i + 1) & 1) * STG,
                           Ahi, Alo, Bhi, Blo, tileM, tileN, (i + 1) << 3, ru4, tid);
            cp_commit();
            asm volatile("cp.async.wait_group 1;" ::: "memory");
        } else {
            asm volatile("cp.async.wait_group 0;" ::: "memory");
        }
        __syncthreads();

        #pragma unroll
        for (int ks = 0; ks < 4; ks++) {
            const int kb = ks * 32 + lcolB;
            uint32_t ah[4][4], al[4][4];
            #pragma unroll
            for (int mi = 0; mi < 4; mi++) {
                uint32_t off = swz((uint32_t)((wm * 64 + mi * 16 + lrow) * 128 + kb));
                ldsm4(ah[mi], stg + off);
                ldsm4(al[mi], stg + OFF_ALO + off);
            }
            #pragma unroll
            for (int nj = 0; nj < 4; nj++) {
                uint32_t off = swz((uint32_t)((wn * 64 + nj * 16 + lrow) * 128 + kb));
                uint32_t bh[4], bl[4];
                ldsm4(bh, stg + OFF_BHI + off);
                ldsm4(bl, stg + OFF_BLO + off);
                #pragma unroll
                for (int mi = 0; mi < 4; mi++) {
                    #pragma unroll
                    for (int lo = 0; lo < 2; lo++) {
                        float* a = acc[mi][nj * 2 + lo];
                        mma_bf16(a, ah[mi], bh[lo], bh[lo + 2]);
                        mma_bf16(a, ah[mi], bl[lo], bl[lo + 2]);
                        mma_bf16(a, al[mi], bh[lo], bh[lo + 2]);
                    }
                }
            }
        }
        __syncthreads();   // all warps done with stage before it is overwritten
    }

    // ---------------- epilogue ----------------
    const int l4 = lane >> 2;
    const int l2 = (lane & 3) * 2;
    #pragma unroll
    for (int mi = 0; mi < 4; mi++) {
        #pragma unroll
        for (int ni = 0; ni < 8; ni++) {
            const int m = tileM + wm * 64 + mi * 16 + l4;
            const int n = tileN + wn * 64 + ni * 8 + l2;
            float c0 = acc[mi][ni][0], c1 = acc[mi][ni][1];
            float c2 = acc[mi][ni][2], c3 = acc[mi][ni][3];
            if (bias) {
                float b0 = __ldg(&bias[n]), b1 = __ldg(&bias[n + 1]);
                c0 += b0; c1 += b1; c2 += b0; c3 += b1;
            }
            const long long r0 = z * sC + (long long)m * N + n;
            const long long r1 = r0 + (long long)8 * N;
            if (Chi) {
                __nv_bfloat16 h0,l0,h1,l1,h2,l2b,h3,l3;
                split1(c0,h0,l0); split1(c1,h1,l1); split1(c2,h2,l2b); split1(c3,h3,l3);
                uint32_t hw0 = (uint32_t)__bfloat16_as_ushort(h0) | ((uint32_t)__bfloat16_as_ushort(h1) << 16);
                uint32_t lw0 = (uint32_t)__bfloat16_as_ushort(l0) | ((uint32_t)__bfloat16_as_ushort(l1) << 16);
                uint32_t hw1 = (uint32_t)__bfloat16_as_ushort(h2) | ((uint32_t)__bfloat16_as_ushort(h3) << 16);
                uint32_t lw1 = (uint32_t)__bfloat16_as_ushort(l2b)| ((uint32_t)__bfloat16_as_ushort(l3) << 16);
                *(uint32_t*)(Chi + r0) = hw0;  *(uint32_t*)(Clo + r0) = lw0;
                *(uint32_t*)(Chi + r1) = hw1;  *(uint32_t*)(Clo + r1) = lw1;
            } else {
                *(float2*)(Cf + r0) = make_float2(c0, c1);
                *(float2*)(Cf + r1) = make_float2(c2, c3);
            }
        }
    }
}

// ===================== small kernels =====================
__global__ __launch_bounds__(256) void split_fp32(
    const float* __restrict__ in, __nv_bfloat16* __restrict__ hi,
    __nv_bfloat16* __restrict__ lo, int n8)
{
    int i = blockIdx.x * 256 + threadIdx.x;
    if (i >= n8) return;
    const float4* p = (const float4*)in;
    float4 a = p[2*i], b = p[2*i+1];
    float vv[8] = {a.x, a.y, a.z, a.w, b.x, b.y, b.z, b.w};
    uint32_t hw[4], lw[4];
    #pragma unroll
    for (int j = 0; j < 4; j++) {
        __nv_bfloat16 h0, l0, h1, l1;
        split1(vv[2*j],   h0, l0);
        split1(vv[2*j+1], h1, l1);
        hw[j] = (uint32_t)__bfloat16_as_ushort(h0) | ((uint32_t)__bfloat16_as_ushort(h1) << 16);
        lw[j] = (uint32_t)__bfloat16_as_ushort(l0) | ((uint32_t)__bfloat16_as_ushort(l1) << 16);
    }
    ((uint4*)hi)[i] = make_uint4(hw[0], hw[1], hw[2], hw[3]);
    ((uint4*)lo)[i] = make_uint4(lw[0], lw[1], lw[2], lw[3]);
}

__global__ __launch_bounds__(256) void wtrans_split(
    const float* __restrict__ W, __nv_bfloat16* __restrict__ Whi,
    __nv_bfloat16* __restrict__ Wlo)
{
    __shared__ float t[32][33];
    const int k0 = blockIdx.x * 32, n0 = blockIdx.y * 32;
    const int tx = threadIdx.x, ty = threadIdx.y;   // block (32,8)
    #pragma unroll
    for (int i = 0; i < 4; i++)
        t[ty + 8*i][tx] = W[(size_t)(k0 + ty + 8*i) * DIM + n0 + tx];
    __syncthreads();
    #pragma unroll
    for (int i = 0; i < 4; i++) {
        float v = t[tx][ty + 8*i];
        __nv_bfloat16 h, l; split1(v, h, l);
        size_t o = (size_t)(n0 + ty + 8*i) * DIM + k0 + tx;
        Whi[o] = h; Wlo[o] = l;
    }
}

// wvo[d] = dot(Wv[d, :], Wo)  for d < DIM;  wvo[DIM] = dot(bv, Wo)
__global__ __launch_bounds__(256) void wvo_dot(
    const float* __restrict__ Wv, const float* __restrict__ bv,
    const float* __restrict__ Wo, float* __restrict__ wvo)
{
    const int row  = (blockIdx.x * blockDim.x + threadIdx.x) >> 5;   // 0..DIM
    const int lane = threadIdx.x & 31;
    if (row > DIM) return;
    const float* src = (row < DIM) ? (Wv + (size_t)row * DIM) : bv;
    float s = 0.f;
    #pragma unroll 8
    for (int i = lane; i < DIM; i += 32) s += src[i] * Wo[i];
    #pragma unroll
    for (int o = 16; o; o >>= 1) s += __shfl_xor_sync(0xffffffffu, s, o);
    if (lane == 0) wvo[row] = s;
}

// vwo[row] = dot(x[row, :], wvo) + wvo[DIM]    (one warp per token row)
__global__ __launch_bounds__(256) void gemv_vwo(
    const float* __restrict__ x, const float* __restrict__ wvo,
    float* __restrict__ vwo)
{
    const int row  = (blockIdx.x * blockDim.x + threadIdx.x) >> 5;
    const int lane = threadIdx.x & 31;
    if (row >= MTOT) return;
    const float4* xr = (const float4*)(x + (size_t)row * DIM);
    const float4* wv = (const float4*)wvo;
    float s = 0.f;
    #pragma unroll 4
    for (int i = lane; i < DIM / 4; i += 32) {
        float4 a = xr[i], b = wv[i];
        s += a.x*b.x + a.y*b.y + a.z*b.z + a.w*b.w;
    }
    #pragma unroll
    for (int o = 16; o; o >>= 1) s += __shfl_xor_sync(0xffffffffu, s, o);
    if (lane == 0) vwo[row] = s + wvo[DIM];
}

// per score row: out = sum_t exp(sc - m) * vwo[t] / sum_t exp(sc - m) + bo
__global__ __launch_bounds__(256) void softmax_dot(
    const float* __restrict__ Sc, const float* __restrict__ vwo,
    const float* __restrict__ bo, float* __restrict__ out)
{
    const size_t row = blockIdx.x;
    const float* p  = Sc  + row * SEQ;
    const float* vw = vwo + (row / SEQ) * SEQ;
    const int tid = threadIdx.x, lane = tid & 31, w = tid >> 5;
    __shared__ float rmax[8], racc[8], rsum[8];

    float vals[8];
    float m = -3.0e38f;
    #pragma unroll
    for (int i = 0; i < 8; i++) { vals[i] = p[tid + i * 256]; m = fmaxf(m, vals[i]); }
    #pragma unroll
    for (int o = 16; o; o >>= 1) m = fmaxf(m, __shfl_xor_sync(0xffffffffu, m, o));
    if (lane == 0) rmax[w] = m;
    __syncthreads();
    m = rmax[0];
    #pragma unroll
    for (int i = 1; i < 8; i++) m = fmaxf(m, rmax[i]);

    float s = 0.f, d = 0.f;
    #pragma unroll
    for (int i = 0; i < 8; i++) {
        float e = __expf(vals[i] - m);
        s += e;
        d += e * vw[tid + i * 256];
    }
    #pragma unroll
    for (int o = 16; o; o >>= 1) {
        s += __shfl_xor_sync(0xffffffffu, s, o);
        d += __shfl_xor_sync(0xffffffffu, d, o);
    }
    if (lane == 0) { rsum[w] = s; racc[w] = d; }
    __syncthreads();
    if (tid == 0) {
        s = rsum[0]; d = racc[0];
        #pragma unroll
        for (int i = 1; i < 8; i++) { s += rsum[i]; d += racc[i]; }
        out[row] = d / s + bo[0];
    }
}

// ===================== launch =====================
extern "C" void kernel_launch(void* const* d_in, const int* in_sizes, int n_in,
                              void* d_out, int out_size)
{
    const float* x  = (const float*)d_in[0];
    const float* Wq = (const float*)d_in[1];
    const float* bq = (const float*)d_in[2];
    const float* Wk = (const float*)d_in[3];
    const float* bk = (const float*)d_in[4];
    const float* Wv = (const float*)d_in[5];
    const float* bv = (const float*)d_in[6];
    const float* Wo = (const float*)d_in[7];
    const float* bo = (const float*)d_in[8];
    float* out = (float*)d_out;

    __nv_bfloat16 *xhi,*xlo,*wqh,*wql,*wkh,*wkl,*qhi,*qlo,*khi,*klo;
    float *sc, *wvo, *vwo;
    cudaGetSymbolAddress((void**)&xhi, g_xhi);   cudaGetSymbolAddress((void**)&xlo, g_xlo);
    cudaGetSymbolAddress((void**)&wqh, g_wqt_hi);cudaGetSymbolAddress((void**)&wql, g_wqt_lo);
    cudaGetSymbolAddress((void**)&wkh, g_wkt_hi);cudaGetSymbolAddress((void**)&wkl, g_wkt_lo);
    cudaGetSymbolAddress((void**)&qhi, g_qhi);   cudaGetSymbolAddress((void**)&qlo, g_qlo);
    cudaGetSymbolAddress((void**)&khi, g_khi);   cudaGetSymbolAddress((void**)&klo, g_klo);
    cudaGetSymbolAddress((void**)&sc,  g_sc);
    cudaGetSymbolAddress((void**)&wvo, g_wvo);
    cudaGetSymbolAddress((void**)&vwo, g_vwo);

    cudaFuncSetAttribute(gemm_hmma_x3, cudaFuncAttributeMaxDynamicSharedMemorySize, GEMM_SMEM);

    const long long sQ  = (long long)SEQ * DIM;
    const long long sSc = (long long)SEQ * SEQ;

    // 1) split x into hi/lo bf16
    split_fp32<<<(MTOT*DIM/8 + 255)/256, 256>>>(x, xhi, xlo, MTOT*DIM/8);

    // 2) transpose+split Wq, Wk
    dim3 wb(32, 8), wg(DIM/32, DIM/32);
    wtrans_split<<<wg, wb>>>(Wq, wqh, wql);
    wtrans_split<<<wg, wb>>>(Wk, wkh, wkl);

    // 3) V path collapsed: wvo = Wv @ Wo (+ bv@Wo), vwo = x @ wvo
    wvo_dot<<<(DIM + 1 + 7) / 8, 256>>>(Wv, bv, Wo, wvo);
    gemv_vwo<<<MTOT / 8, 256>>>(x, wvo, vwo);

    // 4) q,k projections (bf16 hi/lo outputs)
    dim3 gp(DIM/256, MTOT/128, 1);
    gemm_hmma_x3<<<gp, 256, GEMM_SMEM>>>(xhi, xlo, wqh, wql, nullptr, qhi, qlo, bq,
                                         DIM, DIM, 0, 0, 0);
    gemm_hmma_x3<<<gp, 256, GEMM_SMEM>>>(xhi, xlo, wkh, wkl, nullptr, khi, klo, bk,
                                         DIM, DIM, 0, 0, 0);

    // 5) scores = q @ k^T (per batch, NT)
    dim3 gs(SEQ/256, SEQ/128, BATCH);
    gemm_hmma_x3<<<gs, 256, GEMM_SMEM>>>(qhi, qlo, khi, klo, sc, nullptr, nullptr, nullptr,
                                         SEQ, DIM, sQ, sQ, sSc);

    // 6) fused softmax + dot with vwo -> out
    softmax_dot<<<MTOT, 256>>>(sc, vwo, bo, out);
}

// round 6
// speedup vs baseline: 5.1230x; 1.0300x over previous
#include <cuda_runtime.h>
#include <cuda_bf16.h>
#include <cstdint>

#define BATCH 8
#define SEQ   2048
#define DIM   1024
#define MTOT  (BATCH*SEQ)              // 16384
#define NQK   2048                     // fused q|k output width
#define NKT   8                        // k-tiles of 256 per sequence
#define NQT   16                       // q-tiles of 128 per sequence

// ===================== scratch (device globals, allocation-free) =====================
__device__ __align__(16) __nv_bfloat16 g_xhi[(size_t)MTOT*DIM];
__device__ __align__(16) __nv_bfloat16 g_xlo[(size_t)MTOT*DIM];
__device__ __align__(16) __nv_bfloat16 g_wqkt_hi[(size_t)NQK*DIM];   // rows 0..1023 Wq^T, 1024..2047 Wk^T
__device__ __align__(16) __nv_bfloat16 g_wqkt_lo[(size_t)NQK*DIM];
__device__ __align__(16) float         g_qkbias[NQK];
__device__ __align__(16) __nv_bfloat16 g_qkhi[(size_t)MTOT*NQK];     // [token][0:1024]=q, [1024:2048]=k
__device__ __align__(16) __nv_bfloat16 g_qklo[(size_t)MTOT*NQK];
__device__ __align__(16) float         g_wvo[DIM + 1];
__device__ __align__(16) float         g_vwo[(size_t)MTOT];
__device__ __align__(16) float         g_pm[(size_t)BATCH*NQT*NKT*128];
__device__ __align__(16) float         g_psum[(size_t)BATCH*NQT*NKT*128];
__device__ __align__(16) float         g_pd[(size_t)BATCH*NQT*NKT*128];

// ===================== helpers =====================
__device__ __forceinline__ uint32_t smem_u32(const void* p) {
    uint32_t a;
    asm("{ .reg .u64 t; cvta.to.shared.u64 t, %1; cvt.u32.u64 %0, t; }" : "=r"(a) : "l"(p));
    return a;
}
__device__ __forceinline__ void cp16(uint32_t saddr, const void* g) {
    asm volatile("cp.async.cg.shared.global [%0], [%1], 16;" :: "r"(saddr), "l"(g));
}
__device__ __forceinline__ void cp_commit() {
    asm volatile("cp.async.commit_group;" ::: "memory");
}
__device__ __forceinline__ void ldsm4(uint32_t* r, uint32_t addr) {
    asm volatile("ldmatrix.sync.aligned.m8n8.x4.shared.b16 {%0,%1,%2,%3}, [%4];"
                 : "=r"(r[0]), "=r"(r[1]), "=r"(r[2]), "=r"(r[3]) : "r"(addr));
}
__device__ __forceinline__ void mma_bf16(float* c, const uint32_t* a, uint32_t b0, uint32_t b1) {
    asm volatile(
        "mma.sync.aligned.m16n8k16.row.col.f32.bf16.bf16.f32 "
        "{%0,%1,%2,%3},{%4,%5,%6,%7},{%8,%9},{%0,%1,%2,%3};"
        : "+f"(c[0]), "+f"(c[1]), "+f"(c[2]), "+f"(c[3])
        : "r"(a[0]), "r"(a[1]), "r"(a[2]), "r"(a[3]), "r"(b0), "r"(b1));
}
__device__ __forceinline__ void split1(float v, __nv_bfloat16& h, __nv_bfloat16& l) {
    h = __float2bfloat16(v);
    l = __float2bfloat16(v - __bfloat162float(h));
}
__device__ __forceinline__ uint32_t swz(uint32_t off) {   // SW128 swizzle
    return off ^ ((off >> 3) & 0x70);
}

// ===================== shared GEMM mainloop pieces =====================
// Tile 128(M) x 256(N) x 64(K-chunk). 256 threads = 8 warps, warp tile 64x64.
#define STG      98304
#define OFF_ALO  16384
#define OFF_BHI  32768
#define OFF_BLO  65536
#define GEMM_SMEM (2*STG)

__device__ __forceinline__ void prefetch_chunk(
    uint32_t sbase, const __nv_bfloat16* Ahi, const __nv_bfloat16* Alo,
    const __nv_bfloat16* Bhi, const __nv_bfloat16* Blo,
    int rowA0, int rowB0, int ku4, int ldAu4, int ldBu4, int tid)
{
    #pragma unroll
    for (int t = 0; t < 4; t++) {                 // A: 128 rows x 8 u4
        int idx = tid + t * 256;
        int r = idx >> 3, c = idx & 7;
        uint32_t soff = swz((uint32_t)(r * 128 + c * 16));
        size_t gA = (size_t)(rowA0 + r) * ldAu4 + ku4 + c;
        cp16(sbase + soff,           (const uint4*)Ahi + gA);
        cp16(sbase + OFF_ALO + soff, (const uint4*)Alo + gA);
    }
    #pragma unroll
    for (int t = 0; t < 8; t++) {                 // B: 256 rows x 8 u4
        int idx = tid + t * 256;
        int r = idx >> 3, c = idx & 7;
        uint32_t soff = swz((uint32_t)(r * 128 + c * 16));
        size_t gB = (size_t)(rowB0 + r) * ldBu4 + ku4 + c;
        cp16(sbase + OFF_BHI + soff, (const uint4*)Bhi + gB);
        cp16(sbase + OFF_BLO + soff, (const uint4*)Blo + gB);
    }
}

// computes acc[4][8][4] (x3 split); shared by both kernels
#define GEMM_MAINLOOP(ACC, AHI, ALO, BHI, BLO, ROWA0, ROWB0, NK, LDAU4, LDBU4)       \
    prefetch_chunk(sb, AHI, ALO, BHI, BLO, ROWA0, ROWB0, 0, LDAU4, LDBU4, tid);      \
    cp_commit();                                                                     \
    for (int i = 0; i < (NK); i++) {                                                 \
        const uint32_t stg = sb + (uint32_t)(i & 1) * STG;                           \
        if (i + 1 < (NK)) {                                                          \
            prefetch_chunk(sb + (uint32_t)((i + 1) & 1) * STG,                       \
                           AHI, ALO, BHI, BLO, ROWA0, ROWB0, (i + 1) << 3,           \
                           LDAU4, LDBU4, tid);                                       \
            cp_commit();                                                             \
            asm volatile("cp.async.wait_group 1;" ::: "memory");                     \
        } else {                                                                     \
            asm volatile("cp.async.wait_group 0;" ::: "memory");                     \
        }                                                                            \
        __syncthreads();                                                             \
        _Pragma("unroll")                                                            \
        for (int ks = 0; ks < 4; ks++) {                                             \
            const int kb = ks * 32 + lcolB;                                          \
            uint32_t ah[4][4], al[4][4];                                             \
            _Pragma("unroll")                                                        \
            for (int mi = 0; mi < 4; mi++) {                                         \
                uint32_t off = swz((uint32_t)((wm * 64 + mi * 16 + lrow) * 128 + kb));\
                ldsm4(ah[mi], stg + off);                                            \
                ldsm4(al[mi], stg + OFF_ALO + off);                                  \
            }                                                                        \
            _Pragma("unroll")                                                        \
            for (int nj = 0; nj < 4; nj++) {                                         \
                uint32_t off = swz((uint32_t)((wn * 64 + nj * 16 + lrow) * 128 + kb));\
                uint32_t bh[4], bl[4];                                               \
                ldsm4(bh, stg + OFF_BHI + off);                                      \
                ldsm4(bl, stg + OFF_BLO + off);                                      \
                _Pragma("unroll")                                                    \
                for (int mi = 0; mi < 4; mi++) {                                     \
                    _Pragma("unroll")                                                \
                    for (int lo = 0; lo < 2; lo++) {                                 \
                        float* a = ACC[mi][nj * 2 + lo];                             \
                        mma_bf16(a, ah[mi], bh[lo], bh[lo + 2]);                     \
                        mma_bf16(a, ah[mi], bl[lo], bl[lo + 2]);                     \
                        mma_bf16(a, al[mi], bh[lo], bh[lo + 2]);                     \
                    }                                                                \
                }                                                                    \
            }                                                                        \
        }                                                                            \
        __syncthreads();                                                             \
    }

// ===================== kernel 1: fused QK projection =====================
// C[m,n] = sum_k x[m,k] * WqkT[n,k] + qkbias[n], split to bf16 hi/lo
__global__ __launch_bounds__(256, 1) void qkproj(
    const __nv_bfloat16* __restrict__ Ahi, const __nv_bfloat16* __restrict__ Alo,
    const __nv_bfloat16* __restrict__ Bhi, const __nv_bfloat16* __restrict__ Blo,
    __nv_bfloat16* __restrict__ Chi, __nv_bfloat16* __restrict__ Clo,
    const float* __restrict__ bias)
{
    extern __shared__ char smem[];
    const uint32_t sb = smem_u32(smem);
    const int tid  = threadIdx.x;
    const int wid  = tid >> 5;
    const int lane = tid & 31;
    const int tileM = blockIdx.y * 128;
    const int tileN = blockIdx.x * 256;
    const int wm = wid >> 2, wn = wid & 3;
    const int lrow = lane & 15, lcolB = (lane >> 4) * 16;

    float acc[4][8][4];
    #pragma unroll
    for (int mi = 0; mi < 4; mi++)
        #pragma unroll
        for (int ni = 0; ni < 8; ni++)
            #pragma unroll
            for (int q = 0; q < 4; q++) acc[mi][ni][q] = 0.f;

    GEMM_MAINLOOP(acc, Ahi, Alo, Bhi, Blo, tileM, tileN, DIM/64, DIM/8, DIM/8);

    const int l4 = lane >> 2;
    const int l2 = (lane & 3) * 2;
    #pragma unroll
    for (int mi = 0; mi < 4; mi++) {
        #pragma unroll
        for (int ni = 0; ni < 8; ni++) {
            const int m = tileM + wm * 64 + mi * 16 + l4;
            const int n = tileN + wn * 64 + ni * 8 + l2;
            float b0 = __ldg(&bias[n]), b1 = __ldg(&bias[n + 1]);
            float c0 = acc[mi][ni][0] + b0, c1 = acc[mi][ni][1] + b1;
            float c2 = acc[mi][ni][2] + b0, c3 = acc[mi][ni][3] + b1;
            const size_t r0 = (size_t)m * NQK + n;
            const size_t r1 = r0 + (size_t)8 * NQK;
            __nv_bfloat16 h0,l0,h1,l1,h2,l2b,h3,l3;
            split1(c0,h0,l0); split1(c1,h1,l1); split1(c2,h2,l2b); split1(c3,h3,l3);
            *(uint32_t*)(Chi + r0) = (uint32_t)__bfloat16_as_ushort(h0) | ((uint32_t)__bfloat16_as_ushort(h1) << 16);
            *(uint32_t*)(Clo + r0) = (uint32_t)__bfloat16_as_ushort(l0) | ((uint32_t)__bfloat16_as_ushort(l1) << 16);
            *(uint32_t*)(Chi + r1) = (uint32_t)__bfloat16_as_ushort(h2) | ((uint32_t)__bfloat16_as_ushort(h3) << 16);
            *(uint32_t*)(Clo + r1) = (uint32_t)__bfloat16_as_ushort(l2b)| ((uint32_t)__bfloat16_as_ushort(l3) << 16);
        }
    }
}

// ===================== kernel 2: flash-partial scores =====================
// CTA (qt, ky, z): S = q[qt-tile] @ k[ky-tile]^T, then per-row partial
// (m, s=sum e^{S-m}, d=sum e^{S-m}*vwo) over this 256-col tile.
__global__ __launch_bounds__(256, 1) void flash_scores(
    const __nv_bfloat16* __restrict__ qkhi, const __nv_bfloat16* __restrict__ qklo,
    const float* __restrict__ vwo,
    float* __restrict__ pm, float* __restrict__ ps, float* __restrict__ pd)
{
    extern __shared__ char smem[];
    const uint32_t sb = smem_u32(smem);
    const int tid  = threadIdx.x;
    const int wid  = tid >> 5;
    const int lane = tid & 31;
    const int qt = blockIdx.x, ky = blockIdx.y, z = blockIdx.z;
    const int wm = wid >> 2, wn = wid & 3;
    const int lrow = lane & 15, lcolB = (lane >> 4) * 16;

    const int rowA0 = z * SEQ + qt * 128;
    const int rowB0 = z * SEQ + ky * 256;
    const __nv_bfloat16* Ahi = qkhi;          // q at col 0
    const __nv_bfloat16* Alo = qklo;
    const __nv_bfloat16* Bhi = qkhi + 1024;   // k at col 1024
    const __nv_bfloat16* Blo = qklo + 1024;

    float acc[4][8][4];
    #pragma unroll
    for (int mi = 0; mi < 4; mi++)
        #pragma unroll
        for (int ni = 0; ni < 8; ni++)
            #pragma unroll
            for (int q = 0; q < 4; q++) acc[mi][ni][q] = 0.f;

    GEMM_MAINLOOP(acc, Ahi, Alo, Bhi, Blo, rowA0, rowB0, DIM/64, NQK/8, NQK/8);

    // -------- per-tile softmax partials (reuse stage smem for reductions) --------
    float* pmax = (float*)smem;            // [4][128]
    float* psum = (float*)(smem + 2048);   // [4][128]
    float* pdot = (float*)(smem + 4096);   // [4][128]
    float* nm   = (float*)(smem + 6144);   // [128]
    const int l4 = lane >> 2;
    const int l2 = (lane & 3) * 2;

    // 1) tile row max
    #pragma unroll
    for (int mi = 0; mi < 4; mi++) {
        float m0 = -3.0e38f, m1 = -3.0e38f;
        #pragma unroll
        for (int ni = 0; ni < 8; ni++) {
            m0 = fmaxf(m0, fmaxf(acc[mi][ni][0], acc[mi][ni][1]));
            m1 = fmaxf(m1, fmaxf(acc[mi][ni][2], acc[mi][ni][3]));
        }
        #pragma unroll
        for (int o = 1; o <= 2; o <<= 1) {
            m0 = fmaxf(m0, __shfl_xor_sync(0xffffffffu, m0, o));
            m1 = fmaxf(m1, __shfl_xor_sync(0xffffffffu, m1, o));
        }
        if ((lane & 3) == 0) {
            int r0 = wm * 64 + mi * 16 + l4;
            pmax[wn * 128 + r0]     = m0;
            pmax[wn * 128 + r0 + 8] = m1;
        }
    }
    __syncthreads();
    if (tid < 128) {
        float m = fmaxf(fmaxf(pmax[tid], pmax[128 + tid]),
                        fmaxf(pmax[256 + tid], pmax[384 + tid]));
        nm[tid] = m;
    }
    __syncthreads();

    // 2) exp sums + vwo dot
    const float* vw = vwo + (size_t)z * SEQ + ky * 256;
    #pragma unroll
    for (int mi = 0; mi < 4; mi++) {
        const int r0 = wm * 64 + mi * 16 + l4;
        const float m0 = nm[r0], m1 = nm[r0 + 8];
        float s0 = 0.f, d0 = 0.f, s1 = 0.f, d1 = 0.f;
        #pragma unroll
        for (int ni = 0; ni < 8; ni++) {
            const int c = wn * 64 + ni * 8 + l2;
            const float v0 = __ldg(&vw[c]), v1 = __ldg(&vw[c + 1]);
            float e;
            e = __expf(acc[mi][ni][0] - m0); s0 += e; d0 += e * v0;
            e = __expf(acc[mi][ni][1] - m0); s0 += e; d0 += e * v1;
            e = __expf(acc[mi][ni][2] - m1); s1 += e; d1 += e * v0;
            e = __expf(acc[mi][ni][3] - m1); s1 += e; d1 += e * v1;
        }
        #pragma unroll
        for (int o = 1; o <= 2; o <<= 1) {
            s0 += __shfl_xor_sync(0xffffffffu, s0, o);
            d0 += __shfl_xor_sync(0xffffffffu, d0, o);
            s1 += __shfl_xor_sync(0xffffffffu, s1, o);
            d1 += __shfl_xor_sync(0xffffffffu, d1, o);
        }
        if ((lane & 3) == 0) {
            psum[wn * 128 + r0]     = s0;  pdot[wn * 128 + r0]     = d0;
            psum[wn * 128 + r0 + 8] = s1;  pdot[wn * 128 + r0 + 8] = d1;
        }
    }
    __syncthreads();

    // 3) write partials
    if (tid < 128) {
        float s = psum[tid] + psum[128 + tid] + psum[256 + tid] + psum[384 + tid];
        float d = pdot[tid] + pdot[128 + tid] + pdot[256 + tid] + pdot[384 + tid];
        size_t idx = (((size_t)z * NQT + qt) * NKT + ky) * 128 + tid;
        pm[idx] = nm[tid];
        ps[idx] = s;
        pd[idx] = d;
    }
}

// ===================== kernel 3: combine partials =====================
__global__ __launch_bounds__(256) void combine(
    const float* __restrict__ pm, const float* __restrict__ ps,
    const float* __restrict__ pd, const float* __restrict__ bo,
    float* __restrict__ out)
{
    const int row = blockIdx.x * 256 + threadIdx.x;   // 0..16383
    if (row >= MTOT) return;
    const int z = row / SEQ;
    const int sr = row % SEQ;
    const int qt = sr / 128, r = sr % 128;
    const size_t base = (((size_t)z * NQT + qt) * NKT) * 128 + r;

    float M = -3.0e38f;
    #pragma unroll
    for (int k = 0; k < NKT; k++) M = fmaxf(M, pm[base + k * 128]);
    float s = 0.f, d = 0.f;
    #pragma unroll
    for (int k = 0; k < NKT; k++) {
        float c = __expf(pm[base + k * 128] - M);
        s += ps[base + k * 128] * c;
        d += pd[base + k * 128] * c;
    }
    out[row] = d / s + bo[0];
}

// ===================== small kernels =====================
// wvo[d] = dot(Wv[d,:], Wo); wvo[DIM] = dot(bv, Wo)
__global__ __launch_bounds__(256) void wvo_dot(
    const float* __restrict__ Wv, const float* __restrict__ bv,
    const float* __restrict__ Wo, float* __restrict__ wvo)
{
    const int row  = (blockIdx.x * blockDim.x + threadIdx.x) >> 5;
    const int lane = threadIdx.x & 31;
    if (row > DIM) return;
    const float* src = (row < DIM) ? (Wv + (size_t)row * DIM) : bv;
    float s = 0.f;
    #pragma unroll 8
    for (int i = lane; i < DIM; i += 32) s += src[i] * Wo[i];
    #pragma unroll
    for (int o = 16; o; o >>= 1) s += __shfl_xor_sync(0xffffffffu, s, o);
    if (lane == 0) wvo[row] = s;
}

// one warp per token row: split x -> hi/lo bf16 AND vwo[row] = x.wvo + bvwo
__global__ __launch_bounds__(256) void xprep(
    const float* __restrict__ x, const float* __restrict__ wvo,
    __nv_bfloat16* __restrict__ hi, __nv_bfloat16* __restrict__ lo,
    float* __restrict__ vwo_out)
{
    const int row  = (blockIdx.x * blockDim.x + threadIdx.x) >> 5;
    const int lane = threadIdx.x & 31;
    if (row >= MTOT) return;
    const float4* xr = (const float4*)(x + (size_t)row * DIM);
    const float4* wv = (const float4*)wvo;
    uint2* hr = (uint2*)(hi + (size_t)row * DIM);
    uint2* lr = (uint2*)(lo + (size_t)row * DIM);
    float s = 0.f;
    #pragma unroll
    for (int j = 0; j < 8; j++) {
        const int i = lane + j * 32;
        float4 a = __ldg(&xr[i]);
        float4 b = __ldg(&wv[i]);
        s += a.x*b.x + a.y*b.y + a.z*b.z + a.w*b.w;
        __nv_bfloat16 h0,l0,h1,l1,h2,l2,h3,l3;
        split1(a.x,h0,l0); split1(a.y,h1,l1); split1(a.z,h2,l2); split1(a.w,h3,l3);
        uint2 hw, lw;
        hw.x = (uint32_t)__bfloat16_as_ushort(h0) | ((uint32_t)__bfloat16_as_ushort(h1) << 16);
        hw.y = (uint32_t)__bfloat16_as_ushort(h2) | ((uint32_t)__bfloat16_as_ushort(h3) << 16);
        lw.x = (uint32_t)__bfloat16_as_ushort(l0) | ((uint32_t)__bfloat16_as_ushort(l1) << 16);
        lw.y = (uint32_t)__bfloat16_as_ushort(l2) | ((uint32_t)__bfloat16_as_ushort(l3) << 16);
        hr[i] = hw;  lr[i] = lw;
    }
    #pragma unroll
    for (int o = 16; o; o >>= 1) s += __shfl_xor_sync(0xffffffffu, s, o);
    if (lane == 0) vwo_out[row] = s + wvo[DIM];
}

// W [D,D] -> Wt[n][k] = W[k][n], split into hi/lo (output base offsettable)
__global__ __launch_bounds__(256) void wtrans_split(
    const float* __restrict__ W, __nv_bfloat16* __restrict__ Whi,
    __nv_bfloat16* __restrict__ Wlo)
{
    __shared__ float t[32][33];
    const int k0 = blockIdx.x * 32, n0 = blockIdx.y * 32;
    const int tx = threadIdx.x, ty = threadIdx.y;   // block (32,8)
    #pragma unroll
    for (int i = 0; i < 4; i++)
        t[ty + 8*i][tx] = W[(size_t)(k0 + ty + 8*i) * DIM + n0 + tx];
    __syncthreads();
    #pragma unroll
    for (int i = 0; i < 4; i++) {
        float v = t[tx][ty + 8*i];
        __nv_bfloat16 h, l; split1(v, h, l);
        size_t o = (size_t)(n0 + ty + 8*i) * DIM + k0 + tx;
        Whi[o] = h; Wlo[o] = l;
    }
}

__global__ __launch_bounds__(256) void concat_bias(
    const float* __restrict__ bq, const float* __restrict__ bk,
    float* __restrict__ qkb)
{
    int i = blockIdx.x * 256 + threadIdx.x;
    if (i < DIM) qkb[i] = bq[i];
    else if (i < NQK) qkb[i] = bk[i - DIM];
}

// ===================== launch =====================
extern "C" void kernel_launch(void* const* d_in, const int* in_sizes, int n_in,
                              void* d_out, int out_size)
{
    const float* x  = (const float*)d_in[0];
    const float* Wq = (const float*)d_in[1];
    const float* bq = (const float*)d_in[2];
    const float* Wk = (const float*)d_in[3];
    const float* bk = (const float*)d_in[4];
    const float* Wv = (const float*)d_in[5];
    const float* bv = (const float*)d_in[6];
    const float* Wo = (const float*)d_in[7];
    const float* bo = (const float*)d_in[8];
    float* out = (float*)d_out;

    __nv_bfloat16 *xhi,*xlo,*wth,*wtl,*qkh,*qkl;
    float *qkb, *wvo, *vwo, *pm, *ps, *pd;
    cudaGetSymbolAddress((void**)&xhi, g_xhi);    cudaGetSymbolAddress((void**)&xlo, g_xlo);
    cudaGetSymbolAddress((void**)&wth, g_wqkt_hi);cudaGetSymbolAddress((void**)&wtl, g_wqkt_lo);
    cudaGetSymbolAddress((void**)&qkh, g_qkhi);   cudaGetSymbolAddress((void**)&qkl, g_qklo);
    cudaGetSymbolAddress((void**)&qkb, g_qkbias);
    cudaGetSymbolAddress((void**)&wvo, g_wvo);    cudaGetSymbolAddress((void**)&vwo, g_vwo);
    cudaGetSymbolAddress((void**)&pm,  g_pm);
    cudaGetSymbolAddress((void**)&ps,  g_psum);   cudaGetSymbolAddress((void**)&pd,  g_pd);

    cudaFuncSetAttribute(qkproj,       cudaFuncAttributeMaxDynamicSharedMemorySize, GEMM_SMEM);
    cudaFuncSetAttribute(flash_scores, cudaFuncAttributeMaxDynamicSharedMemorySize, GEMM_SMEM);

    // 1) wvo = Wv @ Wo (+ bv.Wo scalar)
    wvo_dot<<<(DIM + 1 + 7) / 8, 256>>>(Wv, bv, Wo, wvo);

    // 2) x -> hi/lo split + vwo = x @ wvo + bvwo (one pass)
    xprep<<<MTOT / 8, 256>>>(x, wvo, xhi, xlo, vwo);

    // 3) weights: Wq^T | Wk^T stacked, split; bias concat
    dim3 wb(32, 8), wg(DIM/32, DIM/32);
    wtrans_split<<<wg, wb>>>(Wq, wth, wtl);
    wtrans_split<<<wg, wb>>>(Wk, wth + (size_t)DIM * DIM, wtl + (size_t)DIM * DIM);
    concat_bias<<<NQK / 256, 256>>>(bq, bk, qkb);

    // 4) fused q|k projection: [16384,1024] x [2048,1024]^T
    dim3 gp(NQK / 256, MTOT / 128, 1);
    qkproj<<<gp, 256, GEMM_SMEM>>>(xhi, xlo, wth, wtl, qkh, qkl, qkb);

    // 5) flash-partial scores + softmax partials + vwo dot
    dim3 gf(NQT, NKT, BATCH);
    flash_scores<<<gf, 256, GEMM_SMEM>>>(qkh, qkl, vwo, pm, ps, pd);

    // 6) combine partials -> out
    combine<<<MTOT / 256, 256>>>(pm, ps, pd, bo, out);
}

// round 8
// speedup vs baseline: 6.3859x; 1.2465x over previous
#include <cuda_runtime.h>
#include <cuda_bf16.h>
#include <cstdint>

#define BATCH 8
#define SEQ   2048
#define DIM   1024
#define MTOT  (BATCH*SEQ)              // 16384
#define NKT   8                        // k-tiles of 256 per sequence
#define NQT   16                       // q-tiles of 128 per sequence

// ===================== scratch (device globals, allocation-free) =====================
__device__ __align__(16) __nv_bfloat16 g_xhi[(size_t)MTOT*DIM];
__device__ __align__(16) __nv_bfloat16 g_xlo[(size_t)MTOT*DIM];
__device__ __align__(16) __nv_bfloat16 g_yhi[(size_t)MTOT*DIM];
__device__ __align__(16) __nv_bfloat16 g_ylo[(size_t)MTOT*DIM];
__device__ __align__(16) __nv_bfloat16 g_wqh[(size_t)DIM*DIM];
__device__ __align__(16) __nv_bfloat16 g_wql[(size_t)DIM*DIM];
__device__ __align__(16) __nv_bfloat16 g_wkh[(size_t)DIM*DIM];
__device__ __align__(16) __nv_bfloat16 g_wkl[(size_t)DIM*DIM];
__device__ __align__(16) float         g_gtpart[(size_t)4*DIM*DIM];   // split-K partials
__device__ __align__(16) __nv_bfloat16 g_gthi[(size_t)DIM*DIM];      // Gt = Wk Wq^T
__device__ __align__(16) __nv_bfloat16 g_gtlo[(size_t)DIM*DIM];
__device__ __align__(16) float         g_wvo[DIM + 1];
__device__ __align__(16) float         g_wkbq[DIM];
__device__ __align__(16) float         g_vwo[(size_t)MTOT];
__device__ __align__(16) float         g_w  [(size_t)MTOT];          // per-token score col-bias
__device__ __align__(16) float         g_pm[(size_t)BATCH*NQT*NKT*128];
__device__ __align__(16) float         g_psum[(size_t)BATCH*NQT*NKT*128];
__device__ __align__(16) float         g_pd[(size_t)BATCH*NQT*NKT*128];

// ===================== helpers =====================
__device__ __forceinline__ uint32_t smem_u32(const void* p) {
    uint32_t a;
    asm("{ .reg .u64 t; cvta.to.shared.u64 t, %1; cvt.u32.u64 %0, t; }" : "=r"(a) : "l"(p));
    return a;
}
__device__ __forceinline__ void cp16(uint32_t saddr, const void* g) {
    asm volatile("cp.async.cg.shared.global [%0], [%1], 16;" :: "r"(saddr), "l"(g));
}
__device__ __forceinline__ void cp_commit() {
    asm volatile("cp.async.commit_group;" ::: "memory");
}
__device__ __forceinline__ void ldsm4(uint32_t* r, uint32_t addr) {
    asm volatile("ldmatrix.sync.aligned.m8n8.x4.shared.b16 {%0,%1,%2,%3}, [%4];"
                 : "=r"(r[0]), "=r"(r[1]), "=r"(r[2]), "=r"(r[3]) : "r"(addr));
}
__device__ __forceinline__ void mma_bf16(float* c, const uint32_t* a, uint32_t b0, uint32_t b1) {
    asm volatile(
        "mma.sync.aligned.m16n8k16.row.col.f32.bf16.bf16.f32 "
        "{%0,%1,%2,%3},{%4,%5,%6,%7},{%8,%9},{%0,%1,%2,%3};"
        : "+f"(c[0]), "+f"(c[1]), "+f"(c[2]), "+f"(c[3])
        : "r"(a[0]), "r"(a[1]), "r"(a[2]), "r"(a[3]), "r"(b0), "r"(b1));
}
__device__ __forceinline__ void split1(float v, __nv_bfloat16& h, __nv_bfloat16& l) {
    h = __float2bfloat16(v);
    l = __float2bfloat16(v - __bfloat162float(h));
}
__device__ __forceinline__ uint32_t swz(uint32_t off) {   // SW128 swizzle
    return off ^ ((off >> 3) & 0x70);
}

// ===================== shared GEMM mainloop =====================
// Tile 128(M) x 256(N) x 64(K-chunk). 256 threads = 8 warps, warp tile 64x64.
#define STG      98304
#define OFF_ALO  16384
#define OFF_BHI  32768
#define OFF_BLO  65536
#define GEMM_SMEM (2*STG)

__device__ __forceinline__ void prefetch_chunk(
    uint32_t sbase, const __nv_bfloat16* Ahi, const __nv_bfloat16* Alo,
    const __nv_bfloat16* Bhi, const __nv_bfloat16* Blo,
    int rowA0, int rowB0, int ku4, int ldAu4, int ldBu4, int tid)
{
    #pragma unroll
    for (int t = 0; t < 4; t++) {                 // A: 128 rows x 8 u4
        int idx = tid + t * 256;
        int r = idx >> 3, c = idx & 7;
        uint32_t soff = swz((uint32_t)(r * 128 + c * 16));
        size_t gA = (size_t)(rowA0 + r) * ldAu4 + ku4 + c;
        cp16(sbase + soff,           (const uint4*)Ahi + gA);
        cp16(sbase + OFF_ALO + soff, (const uint4*)Alo + gA);
    }
    #pragma unroll
    for (int t = 0; t < 8; t++) {                 // B: 256 rows x 8 u4
        int idx = tid + t * 256;
        int r = idx >> 3, c = idx & 7;
        uint32_t soff = swz((uint32_t)(r * 128 + c * 16));
        size_t gB = (size_t)(rowB0 + r) * ldBu4 + ku4 + c;
        cp16(sbase + OFF_BHI + soff, (const uint4*)Bhi + gB);
        cp16(sbase + OFF_BLO + soff, (const uint4*)Blo + gB);
    }
}

#define GEMM_MAINLOOP(ACC, AHI, ALO, BHI, BLO, ROWA0, ROWB0, NK, LDAU4, LDBU4)       \
    prefetch_chunk(sb, AHI, ALO, BHI, BLO, ROWA0, ROWB0, 0, LDAU4, LDBU4, tid);      \
    cp_commit();                                                                     \
    for (int i = 0; i < (NK); i++) {                                                 \
        const uint32_t stg = sb + (uint32_t)(i & 1) * STG;                           \
        if (i + 1 < (NK)) {                                                          \
            prefetch_chunk(sb + (uint32_t)((i + 1) & 1) * STG,                       \
                           AHI, ALO, BHI, BLO, ROWA0, ROWB0, (i + 1) << 3,           \
                           LDAU4, LDBU4, tid);                                       \
            cp_commit();                                                             \
            asm volatile("cp.async.wait_group 1;" ::: "memory");                     \
        } else {                                                                     \
            asm volatile("cp.async.wait_group 0;" ::: "memory");                     \
        }                                                                            \
        __syncthreads();                                                             \
        _Pragma("unroll")                                                            \
        for (int ks = 0; ks < 4; ks++) {                                             \
            const int kb = ks * 32 + lcolB;                                          \
            uint32_t ah[4][4], al[4][4];                                             \
            _Pragma("unroll")                                                        \
            for (int mi = 0; mi < 4; mi++) {                                         \
                uint32_t off = swz((uint32_t)((wm * 64 + mi * 16 + lrow) * 128 + kb));\
                ldsm4(ah[mi], stg + off);                                            \
                ldsm4(al[mi], stg + OFF_ALO + off);                                  \
            }                                                                        \
            _Pragma("unroll")                                                        \
            for (int nj = 0; nj < 4; nj++) {                                         \
                uint32_t off = swz((uint32_t)((wn * 64 + nj * 16 + lrow) * 128 + kb));\
                uint32_t bh[4], bl[4];                                               \
                ldsm4(bh, stg + OFF_BHI + off);                                      \
                ldsm4(bl, stg + OFF_BLO + off);                                      \
                _Pragma("unroll")                                                    \
                for (int mi = 0; mi < 4; mi++) {                                     \
                    _Pragma("unroll")                                                \
                    for (int lo = 0; lo < 2; lo++) {                                 \
                        float* a = ACC[mi][nj * 2 + lo];                             \
                        mma_bf16(a, ah[mi], bh[lo], bh[lo + 2]);                     \
                        mma_bf16(a, ah[mi], bl[lo], bl[lo + 2]);                     \
                        mma_bf16(a, al[mi], bh[lo], bh[lo + 2]);                     \
                    }                                                                \
                }                                                                    \
            }                                                                        \
        }                                                                            \
        __syncthreads();                                                             \
    }

#define DECL_ACC(ACC)                                                                \
    float ACC[4][8][4];                                                              \
    _Pragma("unroll")                                                                \
    for (int mi = 0; mi < 4; mi++)                                                   \
        _Pragma("unroll")                                                            \
        for (int ni = 0; ni < 8; ni++)                                               \
            _Pragma("unroll")                                                        \
            for (int q = 0; q < 4; q++) ACC[mi][ni][q] = 0.f;

// ===================== kernel: Gt split-K partial =====================
// part[z][j,i] = sum_{d in slice z} Wk[j,d]*Wq[i,d]   (x3 split)
__global__ __launch_bounds__(256, 1) void gt_partial(
    const __nv_bfloat16* __restrict__ wkh, const __nv_bfloat16* __restrict__ wkl,
    const __nv_bfloat16* __restrict__ wqh, const __nv_bfloat16* __restrict__ wql,
    float* __restrict__ part)
{
    extern __shared__ char smem[];
    const uint32_t sb = smem_u32(smem);
    const int tid  = threadIdx.x;
    const int wid  = tid >> 5;
    const int lane = tid & 31;
    const int tileM = blockIdx.y * 128;
    const int tileN = blockIdx.x * 256;
    const int kofs  = blockIdx.z * 256;     // elements
    const int wm = wid >> 2, wn = wid & 3;
    const int lrow = lane & 15, lcolB = (lane >> 4) * 16;

    const __nv_bfloat16* Ahi = wkh + kofs;
    const __nv_bfloat16* Alo = wkl + kofs;
    const __nv_bfloat16* Bhi = wqh + kofs;
    const __nv_bfloat16* Blo = wql + kofs;

    DECL_ACC(acc);
    GEMM_MAINLOOP(acc, Ahi, Alo, Bhi, Blo, tileM, tileN, 4, DIM/8, DIM/8);

    float* C = part + (size_t)blockIdx.z * DIM * DIM;
    const int l4 = lane >> 2;
    const int l2 = (lane & 3) * 2;
    #pragma unroll
    for (int mi = 0; mi < 4; mi++) {
        #pragma unroll
        for (int ni = 0; ni < 8; ni++) {
            const int m = tileM + wm * 64 + mi * 16 + l4;
            const int n = tileN + wn * 64 + ni * 8 + l2;
            const size_t r0 = (size_t)m * DIM + n;
            *(float2*)(C + r0)                    = make_float2(acc[mi][ni][0], acc[mi][ni][1]);
            *(float2*)(C + r0 + (size_t)8 * DIM)  = make_float2(acc[mi][ni][2], acc[mi][ni][3]);
        }
    }
}

// sum 4 partials, split to bf16 hi/lo
__global__ __launch_bounds__(256) void gt_reduce_split(
    const float* __restrict__ part, __nv_bfloat16* __restrict__ hi,
    __nv_bfloat16* __restrict__ lo)
{
    const size_t i = (size_t)blockIdx.x * 256 + threadIdx.x;   // uint4 index (8 elems)
    const float4* p = (const float4*)part;
    const size_t n4 = (size_t)DIM * DIM / 4;
    float v[8];
    #pragma unroll
    for (int h = 0; h < 2; h++) {
        float4 s = p[2*i + h];
        #pragma unroll
        for (int z = 1; z < 4; z++) {
            float4 a = p[z * n4 + 2*i + h];
            s.x += a.x; s.y += a.y; s.z += a.z; s.w += a.w;
        }
        v[4*h+0]=s.x; v[4*h+1]=s.y; v[4*h+2]=s.z; v[4*h+3]=s.w;
    }
    uint32_t hw[4], lw[4];
    #pragma unroll
    for (int j = 0; j < 4; j++) {
        __nv_bfloat16 h0,l0,h1,l1;
        split1(v[2*j],h0,l0); split1(v[2*j+1],h1,l1);
        hw[j] = (uint32_t)__bfloat16_as_ushort(h0) | ((uint32_t)__bfloat16_as_ushort(h1) << 16);
        lw[j] = (uint32_t)__bfloat16_as_ushort(l0) | ((uint32_t)__bfloat16_as_ushort(l1) << 16);
    }
    ((uint4*)hi)[i] = make_uint4(hw[0], hw[1], hw[2], hw[3]);
    ((uint4*)lo)[i] = make_uint4(lw[0], lw[1], lw[2], lw[3]);
}

// ===================== kernel: y projection =====================
// y[m,j] = sum_i x[m,i] * Gt[j,i], split to bf16 hi/lo
__global__ __launch_bounds__(256, 1) void yproj(
    const __nv_bfloat16* __restrict__ Ahi, const __nv_bfloat16* __restrict__ Alo,
    const __nv_bfloat16* __restrict__ Bhi, const __nv_bfloat16* __restrict__ Blo,
    __nv_bfloat16* __restrict__ Chi, __nv_bfloat16* __restrict__ Clo)
{
    extern __shared__ char smem[];
    const uint32_t sb = smem_u32(smem);
    const int tid  = threadIdx.x;
    const int wid  = tid >> 5;
    const int lane = tid & 31;
    const int tileM = blockIdx.y * 128;
    const int tileN = blockIdx.x * 256;
    const int wm = wid >> 2, wn = wid & 3;
    const int lrow = lane & 15, lcolB = (lane >> 4) * 16;

    DECL_ACC(acc);
    GEMM_MAINLOOP(acc, Ahi, Alo, Bhi, Blo, tileM, tileN, DIM/64, DIM/8, DIM/8);

    const int l4 = lane >> 2;
    const int l2 = (lane & 3) * 2;
    #pragma unroll
    for (int mi = 0; mi < 4; mi++) {
        #pragma unroll
        for (int ni = 0; ni < 8; ni++) {
            const int m = tileM + wm * 64 + mi * 16 + l4;
            const int n = tileN + wn * 64 + ni * 8 + l2;
            const size_t r0 = (size_t)m * DIM + n;
            const size_t r1 = r0 + (size_t)8 * DIM;
            __nv_bfloat16 h0,l0,h1,l1,h2,l2b,h3,l3;
            split1(acc[mi][ni][0],h0,l0); split1(acc[mi][ni][1],h1,l1);
            split1(acc[mi][ni][2],h2,l2b); split1(acc[mi][ni][3],h3,l3);
            *(uint32_t*)(Chi + r0) = (uint32_t)__bfloat16_as_ushort(h0) | ((uint32_t)__bfloat16_as_ushort(h1) << 16);
            *(uint32_t*)(Clo + r0) = (uint32_t)__bfloat16_as_ushort(l0) | ((uint32_t)__bfloat16_as_ushort(l1) << 16);
            *(uint32_t*)(Chi + r1) = (uint32_t)__bfloat16_as_ushort(h2) | ((uint32_t)__bfloat16_as_ushort(h3) << 16);
            *(uint32_t*)(Clo + r1) = (uint32_t)__bfloat16_as_ushort(l2b)| ((uint32_t)__bfloat16_as_ushort(l3) << 16);
        }
    }
}

// ===================== kernel: flash-partial scores =====================
// S = y[qt-tile] @ x[ky-tile]^T + w[col]; per-row partial (m, sum e, sum e*vwo)
__global__ __launch_bounds__(256, 1) void flash_scores(
    const __nv_bfloat16* __restrict__ yhi, const __nv_bfloat16* __restrict__ ylo,
    const __nv_bfloat16* __restrict__ xhi, const __nv_bfloat16* __restrict__ xlo,
    const float* __restrict__ wbias, const float* __restrict__ vwo,
    float* __restrict__ pm, float* __restrict__ ps, float* __restrict__ pd)
{
    extern __shared__ char smem[];
    const uint32_t sb = smem_u32(smem);
    const int tid  = threadIdx.x;
    const int wid  = tid >> 5;
    const int lane = tid & 31;
    const int qt = blockIdx.x, ky = blockIdx.y, z = blockIdx.z;
    const int wm = wid >> 2, wn = wid & 3;
    const int lrow = lane & 15, lcolB = (lane >> 4) * 16;

    const int rowA0 = z * SEQ + qt * 128;
    const int rowB0 = z * SEQ + ky * 256;

    DECL_ACC(acc);
    GEMM_MAINLOOP(acc, yhi, ylo, xhi, xlo, rowA0, rowB0, DIM/64, DIM/8, DIM/8);

    const int l4 = lane >> 2;
    const int l2 = (lane & 3) * 2;

    // add per-column bias w (fp32, exact)
    const float* wb = wbias + (size_t)z * SEQ + ky * 256;
    const float* vw = vwo   + (size_t)z * SEQ + ky * 256;
    #pragma unroll
    for (int ni = 0; ni < 8; ni++) {
        const int c = wn * 64 + ni * 8 + l2;
        const float w0 = __ldg(&wb[c]), w1 = __ldg(&wb[c + 1]);
        #pragma unroll
        for (int mi = 0; mi < 4; mi++) {
            acc[mi][ni][0] += w0; acc[mi][ni][1] += w1;
            acc[mi][ni][2] += w0; acc[mi][ni][3] += w1;
        }
    }

    float* pmax = (float*)smem;            // [4][128]
    float* psum = (float*)(smem + 2048);
    float* pdot = (float*)(smem + 4096);
    float* nm   = (float*)(smem + 6144);

    // 1) tile row max
    #pragma unroll
    for (int mi = 0; mi < 4; mi++) {
        float m0 = -3.0e38f, m1 = -3.0e38f;
        #pragma unroll
        for (int ni = 0; ni < 8; ni++) {
            m0 = fmaxf(m0, fmaxf(acc[mi][ni][0], acc[mi][ni][1]));
            m1 = fmaxf(m1, fmaxf(acc[mi][ni][2], acc[mi][ni][3]));
        }
        #pragma unroll
        for (int o = 1; o <= 2; o <<= 1) {
            m0 = fmaxf(m0, __shfl_xor_sync(0xffffffffu, m0, o));
            m1 = fmaxf(m1, __shfl_xor_sync(0xffffffffu, m1, o));
        }
        if ((lane & 3) == 0) {
            int r0 = wm * 64 + mi * 16 + l4;
            pmax[wn * 128 + r0]     = m0;
            pmax[wn * 128 + r0 + 8] = m1;
        }
    }
    __syncthreads();
    if (tid < 128) {
        nm[tid] = fmaxf(fmaxf(pmax[tid], pmax[128 + tid]),
                        fmaxf(pmax[256 + tid], pmax[384 + tid]));
    }
    __syncthreads();

    // 2) exp sums + vwo dot
    #pragma unroll
    for (int mi = 0; mi < 4; mi++) {
        const int r0 = wm * 64 + mi * 16 + l4;
        const float m0 = nm[r0], m1 = nm[r0 + 8];
        float s0 = 0.f, d0 = 0.f, s1 = 0.f, d1 = 0.f;
        #pragma unroll
        for (int ni = 0; ni < 8; ni++) {
            const int c = wn * 64 + ni * 8 + l2;
            const float v0 = __ldg(&vw[c]), v1 = __ldg(&vw[c + 1]);
            float e;
            e = __expf(acc[mi][ni][0] - m0); s0 += e; d0 += e * v0;
            e = __expf(acc[mi][ni][1] - m0); s0 += e; d0 += e * v1;
            e = __expf(acc[mi][ni][2] - m1); s1 += e; d1 += e * v0;
            e = __expf(acc[mi][ni][3] - m1); s1 += e; d1 += e * v1;
        }
        #pragma unroll
        for (int o = 1; o <= 2; o <<= 1) {
            s0 += __shfl_xor_sync(0xffffffffu, s0, o);
            d0 += __shfl_xor_sync(0xffffffffu, d0, o);
            s1 += __shfl_xor_sync(0xffffffffu, s1, o);
            d1 += __shfl_xor_sync(0xffffffffu, d1, o);
        }
        if ((lane & 3) == 0) {
            psum[wn * 128 + r0]     = s0;  pdot[wn * 128 + r0]     = d0;
            psum[wn * 128 + r0 + 8] = s1;  pdot[wn * 128 + r0 + 8] = d1;
        }
    }
    __syncthreads();

    if (tid < 128) {
        float s = psum[tid] + psum[128 + tid] + psum[256 + tid] + psum[384 + tid];
        float d = pdot[tid] + pdot[128 + tid] + pdot[256 + tid] + pdot[384 + tid];
        size_t idx = (((size_t)z * NQT + qt) * NKT + ky) * 128 + tid;
        pm[idx] = nm[tid];
        ps[idx] = s;
        pd[idx] = d;
    }
}

// ===================== kernel: combine partials =====================
__global__ __launch_bounds__(256) void combine(
    const float* __restrict__ pm, const float* __restrict__ ps,
    const float* __restrict__ pd, const float* __restrict__ bo,
    float* __restrict__ out)
{
    const int row = blockIdx.x * 256 + threadIdx.x;
    if (row >= MTOT) return;
    const int z = row / SEQ;
    const int sr = row % SEQ;
    const int qt = sr / 128, r = sr % 128;
    const size_t base = (((size_t)z * NQT + qt) * NKT) * 128 + r;

    float M = -3.0e38f;
    #pragma unroll
    for (int k = 0; k < NKT; k++) M = fmaxf(M, pm[base + k * 128]);
    float s = 0.f, d = 0.f;
    #pragma unroll
    for (int k = 0; k < NKT; k++) {
        float c = __expf(pm[base + k * 128] - M);
        s += ps[base + k * 128] * c;
        d += pd[base + k * 128] * c;
    }
    out[row] = d / s + bo[0];
}

// ===================== small kernels =====================
// wvo[d] = dot(Wv[d,:], Wo); wvo[DIM] = dot(bv, Wo)
__global__ __launch_bounds__(256) void wvo_dot(
    const float* __restrict__ Wv, const float* __restrict__ bv,
    const float* __restrict__ Wo, float* __restrict__ wvo)
{
    const int row  = (blockIdx.x * blockDim.x + threadIdx.x) >> 5;
    const int lane = threadIdx.x & 31;
    if (row > DIM) return;
    const float* src = (row < DIM) ? (Wv + (size_t)row * DIM) : bv;
    float s = 0.f;
    #pragma unroll 8
    for (int i = lane; i < DIM; i += 32) s += src[i] * Wo[i];
    #pragma unroll
    for (int o = 16; o; o >>= 1) s += __shfl_xor_sync(0xffffffffu, s, o);
    if (lane == 0) wvo[row] = s;
}

// FIXED: wkbq[d] = dot(Wk[d, :], bq)  — ROW d of Wk dotted with bq
// (term 3 of the expansion: bq·k_t = sum_d x_t[d] * sum_j Wk[d,j] bq[j])
__global__ __launch_bounds__(256) void wkbq_dot(
    const float* __restrict__ Wk, const float* __restrict__ bq,
    float* __restrict__ wkbq)
{
    const int row  = (blockIdx.x * blockDim.x + threadIdx.x) >> 5;
    const int lane = threadIdx.x & 31;
    if (row >= DIM) return;
    const float* src = Wk + (size_t)row * DIM;
    float s = 0.f;
    #pragma unroll 8
    for (int i = lane; i < DIM; i += 32) s += src[i] * bq[i];
    #pragma unroll
    for (int o = 16; o; o >>= 1) s += __shfl_xor_sync(0xffffffffu, s, o);
    if (lane == 0) wkbq[row] = s;
}

// one warp per token: split x -> hi/lo AND vwo = x.wvo + bvwo AND w = x.wkbq
__global__ __launch_bounds__(256) void xprep(
    const float* __restrict__ x, const float* __restrict__ wvo,
    const float* __restrict__ wkbq,
    __nv_bfloat16* __restrict__ hi, __nv_bfloat16* __restrict__ lo,
    float* __restrict__ vwo_out, float* __restrict__ w_out)
{
    const int row  = (blockIdx.x * blockDim.x + threadIdx.x) >> 5;
    const int lane = threadIdx.x & 31;
    if (row >= MTOT) return;
    const float4* xr = (const float4*)(x + (size_t)row * DIM);
    const float4* wv = (const float4*)wvo;
    const float4* wk = (const float4*)wkbq;
    uint2* hr = (uint2*)(hi + (size_t)row * DIM);
    uint2* lr = (uint2*)(lo + (size_t)row * DIM);
    float s = 0.f, t = 0.f;
    #pragma unroll
    for (int j = 0; j < 8; j++) {
        const int i = lane + j * 32;
        float4 a = __ldg(&xr[i]);
        float4 b = __ldg(&wv[i]);
        float4 c = __ldg(&wk[i]);
        s += a.x*b.x + a.y*b.y + a.z*b.z + a.w*b.w;
        t += a.x*c.x + a.y*c.y + a.z*c.z + a.w*c.w;
        __nv_bfloat16 h0,l0,h1,l1,h2,l2,h3,l3;
        split1(a.x,h0,l0); split1(a.y,h1,l1); split1(a.z,h2,l2); split1(a.w,h3,l3);
        uint2 hw, lw;
        hw.x = (uint32_t)__bfloat16_as_ushort(h0) | ((uint32_t)__bfloat16_as_ushort(h1) << 16);
        hw.y = (uint32_t)__bfloat16_as_ushort(h2) | ((uint32_t)__bfloat16_as_ushort(h3) << 16);
        lw.x = (uint32_t)__bfloat16_as_ushort(l0) | ((uint32_t)__bfloat16_as_ushort(l1) << 16);
        lw.y = (uint32_t)__bfloat16_as_ushort(l2) | ((uint32_t)__bfloat16_as_ushort(l3) << 16);
        hr[i] = hw;  lr[i] = lw;
    }
    #pragma unroll
    for (int o = 16; o; o >>= 1) {
        s += __shfl_xor_sync(0xffffffffu, s, o);
        t += __shfl_xor_sync(0xffffffffu, t, o);
    }
    if (lane == 0) { vwo_out[row] = s + wvo[DIM]; w_out[row] = t; }
}

// fp32 -> hi/lo bf16 (for Wq, Wk; K-major already)
__global__ __launch_bounds__(256) void split_fp32(
    const float* __restrict__ in, __nv_bfloat16* __restrict__ hi,
    __nv_bfloat16* __restrict__ lo, int n8)
{
    int i = blockIdx.x * 256 + threadIdx.x;
    if (i >= n8) return;
    const float4* p = (const float4*)in;
    float4 a = p[2*i], b = p[2*i+1];
    float vv[8] = {a.x, a.y, a.z, a.w, b.x, b.y, b.z, b.w};
    uint32_t hw[4], lw[4];
    #pragma unroll
    for (int j = 0; j < 4; j++) {
        __nv_bfloat16 h0, l0, h1, l1;
        split1(vv[2*j],   h0, l0);
        split1(vv[2*j+1], h1, l1);
        hw[j] = (uint32_t)__bfloat16_as_ushort(h0) | ((uint32_t)__bfloat16_as_ushort(h1) << 16);
        lw[j] = (uint32_t)__bfloat16_as_ushort(l0) | ((uint32_t)__bfloat16_as_ushort(l1) << 16);
    }
    ((uint4*)hi)[i] = make_uint4(hw[0], hw[1], hw[2], hw[3]);
    ((uint4*)lo)[i] = make_uint4(lw[0], lw[1], lw[2], lw[3]);
}

// ===================== launch =====================
extern "C" void kernel_launch(void* const* d_in, const int* in_sizes, int n_in,
                              void* d_out, int out_size)
{
    const float* x  = (const float*)d_in[0];
    const float* Wq = (const float*)d_in[1];
    const float* bq = (const float*)d_in[2];
    const float* Wk = (const float*)d_in[3];
    const float* bk = (const float*)d_in[4];
    const float* Wv = (const float*)d_in[5];
    const float* bv = (const float*)d_in[6];
    const float* Wo = (const float*)d_in[7];
    const float* bo = (const float*)d_in[8];
    float* out = (float*)d_out;
    (void)bk;   // cancels in softmax (row-constant)

    __nv_bfloat16 *xhi,*xlo,*yhi,*ylo,*wqh,*wql,*wkh,*wkl,*gth,*gtl;
    float *gtpart,*wvo,*wkbq,*vwo,*w,*pm,*ps,*pd;
    cudaGetSymbolAddress((void**)&xhi, g_xhi);  cudaGetSymbolAddress((void**)&xlo, g_xlo);
    cudaGetSymbolAddress((void**)&yhi, g_yhi);  cudaGetSymbolAddress((void**)&ylo, g_ylo);
    cudaGetSymbolAddress((void**)&wqh, g_wqh);  cudaGetSymbolAddress((void**)&wql, g_wql);
    cudaGetSymbolAddress((void**)&wkh, g_wkh);  cudaGetSymbolAddress((void**)&wkl, g_wkl);
    cudaGetSymbolAddress((void**)&gth, g_gthi); cudaGetSymbolAddress((void**)&gtl, g_gtlo);
    cudaGetSymbolAddress((void**)&gtpart, g_gtpart);
    cudaGetSymbolAddress((void**)&wvo, g_wvo);  cudaGetSymbolAddress((void**)&wkbq, g_wkbq);
    cudaGetSymbolAddress((void**)&vwo, g_vwo);  cudaGetSymbolAddress((void**)&w,   g_w);
    cudaGetSymbolAddress((void**)&pm,  g_pm);
    cudaGetSymbolAddress((void**)&ps,  g_psum); cudaGetSymbolAddress((void**)&pd,  g_pd);

    cudaFuncSetAttribute(gt_partial,   cudaFuncAttributeMaxDynamicSharedMemorySize, GEMM_SMEM);
    cudaFuncSetAttribute(yproj,        cudaFuncAttributeMaxDynamicSharedMemorySize, GEMM_SMEM);
    cudaFuncSetAttribute(flash_scores, cudaFuncAttributeMaxDynamicSharedMemorySize, GEMM_SMEM);

    // 1) small vectors
    wvo_dot<<<(DIM + 1 + 7) / 8, 256>>>(Wv, bv, Wo, wvo);
    wkbq_dot<<<DIM / 8, 256>>>(Wk, bq, wkbq);

    // 2) x -> hi/lo + vwo + w (one pass over x)
    xprep<<<MTOT / 8, 256>>>(x, wvo, wkbq, xhi, xlo, vwo, w);

    // 3) Wq, Wk -> hi/lo bf16 (no transpose needed; d is contiguous = K-major)
    split_fp32<<<DIM*DIM/8/256, 256>>>(Wq, wqh, wql, DIM*DIM/8);
    split_fp32<<<DIM*DIM/8/256, 256>>>(Wk, wkh, wkl, DIM*DIM/8);

    // 4) Gt = Wk @ Wq^T  (split-K x3 HMMA -> fp32 partials -> reduce+split)
    dim3 gg(DIM/256, DIM/128, 4);
    gt_partial<<<gg, 256, GEMM_SMEM>>>(wkh, wkl, wqh, wql, gtpart);
    gt_reduce_split<<<DIM*DIM/8/256, 256>>>(gtpart, gth, gtl);

    // 5) y = x @ Gt^T  [16384,1024] x [1024,1024]^T
    dim3 gy(DIM/256, MTOT/128, 1);
    yproj<<<gy, 256, GEMM_SMEM>>>(xhi, xlo, gth, gtl, yhi, ylo);

    // 6) flash-partial scores (+ col bias w) + softmax partials + vwo dot
    dim3 gf(NQT, NKT, BATCH);
    flash_scores<<<gf, 256, GEMM_SMEM>>>(yhi, ylo, xhi, xlo, w, vwo, pm, ps, pd);

    // 7) combine partials -> out
    combine<<<MTOT / 256, 256>>>(pm, ps, pd, bo, out);
}

// round 9
// speedup vs baseline: 6.5921x; 1.0323x over previous
#include <cuda_runtime.h>
#include <cuda_bf16.h>
#include <cstdint>

#define BATCH 8
#define SEQ   2048
#define DIM   1024
#define MTOT  (BATCH*SEQ)              // 16384
#define NKT   8                        // k-tiles of 256 per sequence
#define NQT   16                       // q-tiles of 128 per sequence

// ===================== scratch (device globals, allocation-free) =====================
__device__ __align__(16) __nv_bfloat16 g_xhi[(size_t)MTOT*DIM];
__device__ __align__(16) __nv_bfloat16 g_xlo[(size_t)MTOT*DIM];
__device__ __align__(16) __nv_bfloat16 g_yhi[(size_t)MTOT*DIM];
__device__ __align__(16) __nv_bfloat16 g_ylo[(size_t)MTOT*DIM];
__device__ __align__(16) __nv_bfloat16 g_wqh[(size_t)DIM*DIM];
__device__ __align__(16) __nv_bfloat16 g_wql[(size_t)DIM*DIM];
__device__ __align__(16) __nv_bfloat16 g_wkh[(size_t)DIM*DIM];
__device__ __align__(16) __nv_bfloat16 g_wkl[(size_t)DIM*DIM];
__device__ __align__(16) float         g_gtpart[(size_t)4*DIM*DIM];   // split-K partials
__device__ __align__(16) __nv_bfloat16 g_gthi[(size_t)DIM*DIM];      // Gt = Wk Wq^T
__device__ __align__(16) __nv_bfloat16 g_gtlo[(size_t)DIM*DIM];
__device__ __align__(16) float         g_wvo[DIM + 1];
__device__ __align__(16) float         g_wkbq[DIM];
__device__ __align__(16) float         g_vwo[(size_t)MTOT];
__device__ __align__(16) float         g_w  [(size_t)MTOT];          // per-token score col-bias
__device__ __align__(16) float         g_pm[(size_t)BATCH*NQT*NKT*128];
__device__ __align__(16) float         g_psum[(size_t)BATCH*NQT*NKT*128];
__device__ __align__(16) float         g_pd[(size_t)BATCH*NQT*NKT*128];

// ===================== helpers =====================
__device__ __forceinline__ uint32_t smem_u32(const void* p) {
    uint32_t a;
    asm("{ .reg .u64 t; cvta.to.shared.u64 t, %1; cvt.u32.u64 %0, t; }" : "=r"(a) : "l"(p));
    return a;
}
__device__ __forceinline__ void cp16(uint32_t saddr, const void* g) {
    asm volatile("cp.async.cg.shared.global [%0], [%1], 16;" :: "r"(saddr), "l"(g));
}
__device__ __forceinline__ void cp_commit() {
    asm volatile("cp.async.commit_group;" ::: "memory");
}
__device__ __forceinline__ void ldsm4(uint32_t* r, uint32_t addr) {
    asm volatile("ldmatrix.sync.aligned.m8n8.x4.shared.b16 {%0,%1,%2,%3}, [%4];"
                 : "=r"(r[0]), "=r"(r[1]), "=r"(r[2]), "=r"(r[3]) : "r"(addr));
}
__device__ __forceinline__ void mma_bf16(float* c, const uint32_t* a, uint32_t b0, uint32_t b1) {
    asm volatile(
        "mma.sync.aligned.m16n8k16.row.col.f32.bf16.bf16.f32 "
        "{%0,%1,%2,%3},{%4,%5,%6,%7},{%8,%9},{%0,%1,%2,%3};"
        : "+f"(c[0]), "+f"(c[1]), "+f"(c[2]), "+f"(c[3])
        : "r"(a[0]), "r"(a[1]), "r"(a[2]), "r"(a[3]), "r"(b0), "r"(b1));
}
__device__ __forceinline__ void split1(float v, __nv_bfloat16& h, __nv_bfloat16& l) {
    h = __float2bfloat16(v);
    l = __float2bfloat16(v - __bfloat162float(h));
}
__device__ __forceinline__ uint32_t swz(uint32_t off) {   // SW128 swizzle
    return off ^ ((off >> 3) & 0x70);
}

// ===================== templated GEMM mainloop =====================
// Tile 128(M) x (NJ*64)(N) x 64(K-chunk). 256 threads = 8 warps.
// Warp tile: 64 rows x NJ*16 cols. NJ=4 -> 128x256 (stage 96KB), NJ=2 -> 128x128 (stage 64KB).
template<int NJ>
struct ML {
    static constexpr int BROWS   = NJ * 64;
    static constexpr int OFF_ALO = 16384;
    static constexpr int OFF_BHI = 32768;
    static constexpr int OFF_BLO = 32768 + NJ * 8192;
    static constexpr int STG     = 32768 + NJ * 16384;
};

template<int NJ>
__device__ __forceinline__ void prefetch_chunk(
    uint32_t sbase, const __nv_bfloat16* Ahi, const __nv_bfloat16* Alo,
    const __nv_bfloat16* Bhi, const __nv_bfloat16* Blo,
    int rowA0, int rowB0, int ku4, int ldAu4, int ldBu4, int tid)
{
    #pragma unroll
    for (int t = 0; t < 4; t++) {                 // A: 128 rows x 8 u4
        int idx = tid + t * 256;
        int r = idx >> 3, c = idx & 7;
        uint32_t soff = swz((uint32_t)(r * 128 + c * 16));
        size_t gA = (size_t)(rowA0 + r) * ldAu4 + ku4 + c;
        cp16(sbase + soff,               (const uint4*)Ahi + gA);
        cp16(sbase + ML<NJ>::OFF_ALO + soff, (const uint4*)Alo + gA);
    }
    #pragma unroll
    for (int t = 0; t < NJ * 2; t++) {            // B: NJ*64 rows x 8 u4
        int idx = tid + t * 256;
        int r = idx >> 3, c = idx & 7;
        uint32_t soff = swz((uint32_t)(r * 128 + c * 16));
        size_t gB = (size_t)(rowB0 + r) * ldBu4 + ku4 + c;
        cp16(sbase + ML<NJ>::OFF_BHI + soff, (const uint4*)Bhi + gB);
        cp16(sbase + ML<NJ>::OFF_BLO + soff, (const uint4*)Blo + gB);
    }
}

// Single barrier per chunk: prefetch(i+1) issued AFTER wait+sync of chunk i.
// Safety: buf (i+1)&1 == buf (i-1)&1, and every warp finished compute(i-1)
// before passing the sync at the top of iteration i.
template<int NJ>
__device__ __forceinline__ void gemm_mainloop(
    float (&acc)[4][2*NJ][4], uint32_t sb,
    const __nv_bfloat16* Ahi, const __nv_bfloat16* Alo,
    const __nv_bfloat16* Bhi, const __nv_bfloat16* Blo,
    int rowA0, int rowB0, int nk, int ldAu4, int ldBu4,
    int tid, int wm, int wn, int lrow, int lcolB)
{
    prefetch_chunk<NJ>(sb, Ahi, Alo, Bhi, Blo, rowA0, rowB0, 0, ldAu4, ldBu4, tid);
    cp_commit();

    for (int i = 0; i < nk; i++) {
        const uint32_t stg = sb + (uint32_t)(i & 1) * ML<NJ>::STG;
        asm volatile("cp.async.wait_group 0;" ::: "memory");
        __syncthreads();
        if (i + 1 < nk) {
            prefetch_chunk<NJ>(sb + (uint32_t)((i + 1) & 1) * ML<NJ>::STG,
                               Ahi, Alo, Bhi, Blo, rowA0, rowB0, (i + 1) << 3,
                               ldAu4, ldBu4, tid);
            cp_commit();
        }
        #pragma unroll
        for (int ks = 0; ks < 4; ks++) {
            const int kb = ks * 32 + lcolB;
            uint32_t ah[4][4], al[4][4];
            #pragma unroll
            for (int mi = 0; mi < 4; mi++) {
                uint32_t off = swz((uint32_t)((wm * 64 + mi * 16 + lrow) * 128 + kb));
                ldsm4(ah[mi], stg + off);
                ldsm4(al[mi], stg + ML<NJ>::OFF_ALO + off);
            }
            #pragma unroll
            for (int nj = 0; nj < NJ; nj++) {
                uint32_t off = swz((uint32_t)((wn * (NJ * 16) + nj * 16 + lrow) * 128 + kb));
                uint32_t bh[4], bl[4];
                ldsm4(bh, stg + ML<NJ>::OFF_BHI + off);
                ldsm4(bl, stg + ML<NJ>::OFF_BLO + off);
                #pragma unroll
                for (int mi = 0; mi < 4; mi++) {
                    #pragma unroll
                    for (int lo = 0; lo < 2; lo++) {
                        float* a = acc[mi][nj * 2 + lo];
                        mma_bf16(a, ah[mi], bh[lo], bh[lo + 2]);
                        mma_bf16(a, ah[mi], bl[lo], bl[lo + 2]);
                        mma_bf16(a, al[mi], bh[lo], bh[lo + 2]);
                    }
                }
            }
        }
    }
    // NOTE: no trailing sync. Callers reusing stage-0 smem may only touch it if
    // nk is even (last chunk lives in stage 1) — true for all call sites (nk=16 or 4).
}

#define DECL_ACC(ACC, NJ2)                                                           \
    float ACC[4][NJ2][4];                                                            \
    _Pragma("unroll")                                                                \
    for (int mi = 0; mi < 4; mi++)                                                   \
        _Pragma("unroll")                                                            \
        for (int ni = 0; ni < (NJ2); ni++)                                           \
            _Pragma("unroll")                                                        \
            for (int q = 0; q < 4; q++) ACC[mi][ni][q] = 0.f;

// ===================== kernel: Gt split-K partial (NJ=4) =====================
__global__ __launch_bounds__(256, 1) void gt_partial(
    const __nv_bfloat16* __restrict__ wkh, const __nv_bfloat16* __restrict__ wkl,
    const __nv_bfloat16* __restrict__ wqh, const __nv_bfloat16* __restrict__ wql,
    float* __restrict__ part)
{
    extern __shared__ char smem[];
    const uint32_t sb = smem_u32(smem);
    const int tid  = threadIdx.x;
    const int wid  = tid >> 5;
    const int lane = tid & 31;
    const int tileM = blockIdx.y * 128;
    const int tileN = blockIdx.x * 256;
    const int kofs  = blockIdx.z * 256;
    const int wm = wid >> 2, wn = wid & 3;
    const int lrow = lane & 15, lcolB = (lane >> 4) * 16;

    DECL_ACC(acc, 8);
    gemm_mainloop<4>(acc, sb, wkh + kofs, wkl + kofs, wqh + kofs, wql + kofs,
                     tileM, tileN, 4, DIM/8, DIM/8, tid, wm, wn, lrow, lcolB);

    float* C = part + (size_t)blockIdx.z * DIM * DIM;
    const int l4 = lane >> 2;
    const int l2 = (lane & 3) * 2;
    #pragma unroll
    for (int mi = 0; mi < 4; mi++) {
        #pragma unroll
        for (int ni = 0; ni < 8; ni++) {
            const int m = tileM + wm * 64 + mi * 16 + l4;
            const int n = tileN + wn * 64 + ni * 8 + l2;
            const size_t r0 = (size_t)m * DIM + n;
            *(float2*)(C + r0)                   = make_float2(acc[mi][ni][0], acc[mi][ni][1]);
            *(float2*)(C + r0 + (size_t)8 * DIM) = make_float2(acc[mi][ni][2], acc[mi][ni][3]);
        }
    }
}

// sum 4 partials, split to bf16 hi/lo
__global__ __launch_bounds__(256) void gt_reduce_split(
    const float* __restrict__ part, __nv_bfloat16* __restrict__ hi,
    __nv_bfloat16* __restrict__ lo)
{
    const size_t i = (size_t)blockIdx.x * 256 + threadIdx.x;
    const float4* p = (const float4*)part;
    const size_t n4 = (size_t)DIM * DIM / 4;
    float v[8];
    #pragma unroll
    for (int h = 0; h < 2; h++) {
        float4 s = p[2*i + h];
        #pragma unroll
        for (int z = 1; z < 4; z++) {
            float4 a = p[z * n4 + 2*i + h];
            s.x += a.x; s.y += a.y; s.z += a.z; s.w += a.w;
        }
        v[4*h+0]=s.x; v[4*h+1]=s.y; v[4*h+2]=s.z; v[4*h+3]=s.w;
    }
    uint32_t hw[4], lw[4];
    #pragma unroll
    for (int j = 0; j < 4; j++) {
        __nv_bfloat16 h0,l0,h1,l1;
        split1(v[2*j],h0,l0); split1(v[2*j+1],h1,l1);
        hw[j] = (uint32_t)__bfloat16_as_ushort(h0) | ((uint32_t)__bfloat16_as_ushort(h1) << 16);
        lw[j] = (uint32_t)__bfloat16_as_ushort(l0) | ((uint32_t)__bfloat16_as_ushort(l1) << 16);
    }
    ((uint4*)hi)[i] = make_uint4(hw[0], hw[1], hw[2], hw[3]);
    ((uint4*)lo)[i] = make_uint4(lw[0], lw[1], lw[2], lw[3]);
}

// ===================== kernel: y projection (NJ=2, 128x128, 1024 CTAs) ==========
__global__ __launch_bounds__(256, 1) void yproj(
    const __nv_bfloat16* __restrict__ Ahi, const __nv_bfloat16* __restrict__ Alo,
    const __nv_bfloat16* __restrict__ Bhi, const __nv_bfloat16* __restrict__ Blo,
    __nv_bfloat16* __restrict__ Chi, __nv_bfloat16* __restrict__ Clo)
{
    extern __shared__ char smem[];
    const uint32_t sb = smem_u32(smem);
    const int tid  = threadIdx.x;
    const int wid  = tid >> 5;
    const int lane = tid & 31;
    const int tileM = blockIdx.y * 128;
    const int tileN = blockIdx.x * 128;
    const int wm = wid >> 2, wn = wid & 3;
    const int lrow = lane & 15, lcolB = (lane >> 4) * 16;

    DECL_ACC(acc, 4);
    gemm_mainloop<2>(acc, sb, Ahi, Alo, Bhi, Blo, tileM, tileN, DIM/64,
                     DIM/8, DIM/8, tid, wm, wn, lrow, lcolB);

    const int l4 = lane >> 2;
    const int l2 = (lane & 3) * 2;
    #pragma unroll
    for (int mi = 0; mi < 4; mi++) {
        #pragma unroll
        for (int ni = 0; ni < 4; ni++) {
            const int m = tileM + wm * 64 + mi * 16 + l4;
            const int n = tileN + wn * 32 + ni * 8 + l2;
            const size_t r0 = (size_t)m * DIM + n;
            const size_t r1 = r0 + (size_t)8 * DIM;
            __nv_bfloat16 h0,l0,h1,l1,h2,l2b,h3,l3;
            split1(acc[mi][ni][0],h0,l0); split1(acc[mi][ni][1],h1,l1);
            split1(acc[mi][ni][2],h2,l2b); split1(acc[mi][ni][3],h3,l3);
            *(uint32_t*)(Chi + r0) = (uint32_t)__bfloat16_as_ushort(h0) | ((uint32_t)__bfloat16_as_ushort(h1) << 16);
            *(uint32_t*)(Clo + r0) = (uint32_t)__bfloat16_as_ushort(l0) | ((uint32_t)__bfloat16_as_ushort(l1) << 16);
            *(uint32_t*)(Chi + r1) = (uint32_t)__bfloat16_as_ushort(h2) | ((uint32_t)__bfloat16_as_ushort(h3) << 16);
            *(uint32_t*)(Clo + r1) = (uint32_t)__bfloat16_as_ushort(l2b)| ((uint32_t)__bfloat16_as_ushort(l3) << 16);
        }
    }
}

// ===================== kernel: flash-partial scores (NJ=4) =====================
__global__ __launch_bounds__(256, 1) void flash_scores(
    const __nv_bfloat16* __restrict__ yhi, const __nv_bfloat16* __restrict__ ylo,
    const __nv_bfloat16* __restrict__ xhi, const __nv_bfloat16* __restrict__ xlo,
    const float* __restrict__ wbias, const float* __restrict__ vwo,
    float* __restrict__ pm, float* __restrict__ ps, float* __restrict__ pd)
{
    extern __shared__ char smem[];
    const uint32_t sb = smem_u32(smem);
    const int tid  = threadIdx.x;
    const int wid  = tid >> 5;
    const int lane = tid & 31;
    const int qt = blockIdx.x, ky = blockIdx.y, z = blockIdx.z;
    const int wm = wid >> 2, wn = wid & 3;
    const int lrow = lane & 15, lcolB = (lane >> 4) * 16;

    const int rowA0 = z * SEQ + qt * 128;
    const int rowB0 = z * SEQ + ky * 256;

    DECL_ACC(acc, 8);
    gemm_mainloop<4>(acc, sb, yhi, ylo, xhi, xlo, rowA0, rowB0, DIM/64,
                     DIM/8, DIM/8, tid, wm, wn, lrow, lcolB);

    const int l4 = lane >> 2;
    const int l2 = (lane & 3) * 2;

    // add per-column bias w (fp32, exact)
    const float* wb = wbias + (size_t)z * SEQ + ky * 256;
    const float* vw = vwo   + (size_t)z * SEQ + ky * 256;
    #pragma unroll
    for (int ni = 0; ni < 8; ni++) {
        const int c = wn * 64 + ni * 8 + l2;
        const float w0 = __ldg(&wb[c]), w1 = __ldg(&wb[c + 1]);
        #pragma unroll
        for (int mi = 0; mi < 4; mi++) {
            acc[mi][ni][0] += w0; acc[mi][ni][1] += w1;
            acc[mi][ni][2] += w0; acc[mi][ni][3] += w1;
        }
    }

    // stats scratch lives in stage-0 smem; last chunk computed from stage 1
    // (nk=16 even), so no extra sync needed before writing here.
    float* pmax = (float*)smem;            // [4][128]
    float* psum = (float*)(smem + 2048);
    float* pdot = (float*)(smem + 4096);
    float* nm   = (float*)(smem + 6144);

    // 1) tile row max
    #pragma unroll
    for (int mi = 0; mi < 4; mi++) {
        float m0 = -3.0e38f, m1 = -3.0e38f;
        #pragma unroll
        for (int ni = 0; ni < 8; ni++) {
            m0 = fmaxf(m0, fmaxf(acc[mi][ni][0], acc[mi][ni][1]));
            m1 = fmaxf(m1, fmaxf(acc[mi][ni][2], acc[mi][ni][3]));
        }
        #pragma unroll
        for (int o = 1; o <= 2; o <<= 1) {
            m0 = fmaxf(m0, __shfl_xor_sync(0xffffffffu, m0, o));
            m1 = fmaxf(m1, __shfl_xor_sync(0xffffffffu, m1, o));
        }
        if ((lane & 3) == 0) {
            int r0 = wm * 64 + mi * 16 + l4;
            pmax[wn * 128 + r0]     = m0;
            pmax[wn * 128 + r0 + 8] = m1;
        }
    }
    __syncthreads();
    if (tid < 128) {
        nm[tid] = fmaxf(fmaxf(pmax[tid], pmax[128 + tid]),
                        fmaxf(pmax[256 + tid], pmax[384 + tid]));
    }
    __syncthreads();

    // 2) exp sums + vwo dot
    #pragma unroll
    for (int mi = 0; mi < 4; mi++) {
        const int r0 = wm * 64 + mi * 16 + l4;
        const float m0 = nm[r0], m1 = nm[r0 + 8];
        float s0 = 0.f, d0 = 0.f, s1 = 0.f, d1 = 0.f;
        #pragma unroll
        for (int ni = 0; ni < 8; ni++) {
            const int c = wn * 64 + ni * 8 + l2;
            const float v0 = __ldg(&vw[c]), v1 = __ldg(&vw[c + 1]);
            float e;
            e = __expf(acc[mi][ni][0] - m0); s0 += e; d0 += e * v0;
            e = __expf(acc[mi][ni][1] - m0); s0 += e; d0 += e * v1;
            e = __expf(acc[mi][ni][2] - m1); s1 += e; d1 += e * v0;
            e = __expf(acc[mi][ni][3] - m1); s1 += e; d1 += e * v1;
        }
        #pragma unroll
        for (int o = 1; o <= 2; o <<= 1) {
            s0 += __shfl_xor_sync(0xffffffffu, s0, o);
            d0 += __shfl_xor_sync(0xffffffffu, d0, o);
            s1 += __shfl_xor_sync(0xffffffffu, s1, o);
            d1 += __shfl_xor_sync(0xffffffffu, d1, o);
        }
        if ((lane & 3) == 0) {
            psum[wn * 128 + r0]     = s0;  pdot[wn * 128 + r0]     = d0;
            psum[wn * 128 + r0 + 8] = s1;  pdot[wn * 128 + r0 + 8] = d1;
        }
    }
    __syncthreads();

    if (tid < 128) {
        float s = psum[tid] + psum[128 + tid] + psum[256 + tid] + psum[384 + tid];
        float d = pdot[tid] + pdot[128 + tid] + pdot[256 + tid] + pdot[384 + tid];
        size_t idx = (((size_t)z * NQT + qt) * NKT + ky) * 128 + tid;
        pm[idx] = nm[tid];
        ps[idx] = s;
        pd[idx] = d;
    }
}

// ===================== kernel: combine partials =====================
__global__ __launch_bounds__(256) void combine(
    const float* __restrict__ pm, const float* __restrict__ ps,
    const float* __restrict__ pd, const float* __restrict__ bo,
    float* __restrict__ out)
{
    const int row = blockIdx.x * 256 + threadIdx.x;
    if (row >= MTOT) return;
    const int z = row / SEQ;
    const int sr = row % SEQ;
    const int qt = sr / 128, r = sr % 128;
    const size_t base = (((size_t)z * NQT + qt) * NKT) * 128 + r;

    float M = -3.0e38f;
    #pragma unroll
    for (int k = 0; k < NKT; k++) M = fmaxf(M, pm[base + k * 128]);
    float s = 0.f, d = 0.f;
    #pragma unroll
    for (int k = 0; k < NKT; k++) {
        float c = __expf(pm[base + k * 128] - M);
        s += ps[base + k * 128] * c;
        d += pd[base + k * 128] * c;
    }
    out[row] = d / s + bo[0];
}

// ===================== small kernels =====================
__global__ __launch_bounds__(256) void wvo_dot(
    const float* __restrict__ Wv, const float* __restrict__ bv,
    const float* __restrict__ Wo, float* __restrict__ wvo)
{
    const int row  = (blockIdx.x * blockDim.x + threadIdx.x) >> 5;
    const int lane = threadIdx.x & 31;
    if (row > DIM) return;
    const float* src = (row < DIM) ? (Wv + (size_t)row * DIM) : bv;
    float s = 0.f;
    #pragma unroll 8
    for (int i = lane; i < DIM; i += 32) s += src[i] * Wo[i];
    #pragma unroll
    for (int o = 16; o; o >>= 1) s += __shfl_xor_sync(0xffffffffu, s, o);
    if (lane == 0) wvo[row] = s;
}

// wkbq[d] = dot(Wk[d, :], bq)
__global__ __launch_bounds__(256) void wkbq_dot(
    const float* __restrict__ Wk, const float* __restrict__ bq,
    float* __restrict__ wkbq)
{
    const int row  = (blockIdx.x * blockDim.x + threadIdx.x) >> 5;
    const int lane = threadIdx.x & 31;
    if (row >= DIM) return;
    const float* src = Wk + (size_t)row * DIM;
    float s = 0.f;
    #pragma unroll 8
    for (int i = lane; i < DIM; i += 32) s += src[i] * bq[i];
    #pragma unroll
    for (int o = 16; o; o >>= 1) s += __shfl_xor_sync(0xffffffffu, s, o);
    if (lane == 0) wkbq[row] = s;
}

// one warp per token: split x -> hi/lo AND vwo = x.wvo + bvwo AND w = x.wkbq
__global__ __launch_bounds__(256) void xprep(
    const float* __restrict__ x, const float* __restrict__ wvo,
    const float* __restrict__ wkbq,
    __nv_bfloat16* __restrict__ hi, __nv_bfloat16* __restrict__ lo,
    float* __restrict__ vwo_out, float* __restrict__ w_out)
{
    const int row  = (blockIdx.x * blockDim.x + threadIdx.x) >> 5;
    const int lane = threadIdx.x & 31;
    if (row >= MTOT) return;
    const float4* xr = (const float4*)(x + (size_t)row * DIM);
    const float4* wv = (const float4*)wvo;
    const float4* wk = (const float4*)wkbq;
    uint2* hr = (uint2*)(hi + (size_t)row * DIM);
    uint2* lr = (uint2*)(lo + (size_t)row * DIM);
    float s = 0.f, t = 0.f;
    #pragma unroll
    for (int j = 0; j < 8; j++) {
        const int i = lane + j * 32;
        float4 a = __ldg(&xr[i]);
        float4 b = __ldg(&wv[i]);
        float4 c = __ldg(&wk[i]);
        s += a.x*b.x + a.y*b.y + a.z*b.z + a.w*b.w;
        t += a.x*c.x + a.y*c.y + a.z*c.z + a.w*c.w;
        __nv_bfloat16 h0,l0,h1,l1,h2,l2,h3,l3;
        split1(a.x,h0,l0); split1(a.y,h1,l1); split1(a.z,h2,l2); split1(a.w,h3,l3);
        uint2 hw, lw;
        hw.x = (uint32_t)__bfloat16_as_ushort(h0) | ((uint32_t)__bfloat16_as_ushort(h1) << 16);
        hw.y = (uint32_t)__bfloat16_as_ushort(h2) | ((uint32_t)__bfloat16_as_ushort(h3) << 16);
        lw.x = (uint32_t)__bfloat16_as_ushort(l0) | ((uint32_t)__bfloat16_as_ushort(l1) << 16);
        lw.y = (uint32_t)__bfloat16_as_ushort(l2) | ((uint32_t)__bfloat16_as_ushort(l3) << 16);
        hr[i] = hw;  lr[i] = lw;
    }
    #pragma unroll
    for (int o = 16; o; o >>= 1) {
        s += __shfl_xor_sync(0xffffffffu, s, o);
        t += __shfl_xor_sync(0xffffffffu, t, o);
    }
    if (lane == 0) { vwo_out[row] = s + wvo[DIM]; w_out[row] = t; }
}

// fp32 -> hi/lo bf16
__global__ __launch_bounds__(256) void split_fp32(
    const float* __restrict__ in, __nv_bfloat16* __restrict__ hi,
    __nv_bfloat16* __restrict__ lo, int n8)
{
    int i = blockIdx.x * 256 + threadIdx.x;
    if (i >= n8) return;
    const float4* p = (const float4*)in;
    float4 a = p[2*i], b = p[2*i+1];
    float vv[8] = {a.x, a.y, a.z, a.w, b.x, b.y, b.z, b.w};
    uint32_t hw[4], lw[4];
    #pragma unroll
    for (int j = 0; j < 4; j++) {
        __nv_bfloat16 h0, l0, h1, l1;
        split1(vv[2*j],   h0, l0);
        split1(vv[2*j+1], h1, l1);
        hw[j] = (uint32_t)__bfloat16_as_ushort(h0) | ((uint32_t)__bfloat16_as_ushort(h1) << 16);
        lw[j] = (uint32_t)__bfloat16_as_ushort(l0) | ((uint32_t)__bfloat16_as_ushort(l1) << 16);
    }
    ((uint4*)hi)[i] = make_uint4(hw[0], hw[1], hw[2], hw[3]);
    ((uint4*)lo)[i] = make_uint4(lw[0], lw[1], lw[2], lw[3]);
}

// ===================== launch =====================
extern "C" void kernel_launch(void* const* d_in, const int* in_sizes, int n_in,
                              void* d_out, int out_size)
{
    const float* x  = (const float*)d_in[0];
    const float* Wq = (const float*)d_in[1];
    const float* bq = (const float*)d_in[2];
    const float* Wk = (const float*)d_in[3];
    const float* bk = (const float*)d_in[4];
    const float* Wv = (const float*)d_in[5];
    const float* bv = (const float*)d_in[6];
    const float* Wo = (const float*)d_in[7];
    const float* bo = (const float*)d_in[8];
    float* out = (float*)d_out;
    (void)bk;   // cancels in softmax (row-constant)

    __nv_bfloat16 *xhi,*xlo,*yhi,*ylo,*wqh,*wql,*wkh,*wkl,*gth,*gtl;
    float *gtpart,*wvo,*wkbq,*vwo,*w,*pm,*ps,*pd;
    cudaGetSymbolAddress((void**)&xhi, g_xhi);  cudaGetSymbolAddress((void**)&xlo, g_xlo);
    cudaGetSymbolAddress((void**)&yhi, g_yhi);  cudaGetSymbolAddress((void**)&ylo, g_ylo);
    cudaGetSymbolAddress((void**)&wqh, g_wqh);  cudaGetSymbolAddress((void**)&wql, g_wql);
    cudaGetSymbolAddress((void**)&wkh, g_wkh);  cudaGetSymbolAddress((void**)&wkl, g_wkl);
    cudaGetSymbolAddress((void**)&gth, g_gthi); cudaGetSymbolAddress((void**)&gtl, g_gtlo);
    cudaGetSymbolAddress((void**)&gtpart, g_gtpart);
    cudaGetSymbolAddress((void**)&wvo, g_wvo);  cudaGetSymbolAddress((void**)&wkbq, g_wkbq);
    cudaGetSymbolAddress((void**)&vwo, g_vwo);  cudaGetSymbolAddress((void**)&w,   g_w);
    cudaGetSymbolAddress((void**)&pm,  g_pm);
    cudaGetSymbolAddress((void**)&ps,  g_psum); cudaGetSymbolAddress((void**)&pd,  g_pd);

    const int SM4 = 2 * ML<4>::STG;   // 196608
    const int SM2 = 2 * ML<2>::STG;   // 131072
    cudaFuncSetAttribute(gt_partial,   cudaFuncAttributeMaxDynamicSharedMemorySize, SM4);
    cudaFuncSetAttribute(yproj,        cudaFuncAttributeMaxDynamicSharedMemorySize, SM2);
    cudaFuncSetAttribute(flash_scores, cudaFuncAttributeMaxDynamicSharedMemorySize, SM4);

    // 1) small vectors
    wvo_dot<<<(DIM + 1 + 7) / 8, 256>>>(Wv, bv, Wo, wvo);
    wkbq_dot<<<DIM / 8, 256>>>(Wk, bq, wkbq);

    // 2) x -> hi/lo + vwo + w (one pass over x)
    xprep<<<MTOT / 8, 256>>>(x, wvo, wkbq, xhi, xlo, vwo, w);

    // 3) Wq, Wk -> hi/lo bf16 (d contiguous = K-major already)
    split_fp32<<<DIM*DIM/8/256, 256>>>(Wq, wqh, wql, DIM*DIM/8);
    split_fp32<<<DIM*DIM/8/256, 256>>>(Wk, wkh, wkl, DIM*DIM/8);

    // 4) Gt = Wk @ Wq^T  (split-K x3 HMMA -> fp32 partials -> reduce+split)
    dim3 gg(DIM/256, DIM/128, 4);
    gt_partial<<<gg, 256, SM4>>>(wkh, wkl, wqh, wql, gtpart);
    gt_reduce_split<<<DIM*DIM/8/256, 256>>>(gtpart, gth, gtl);

    // 5) y = x @ Gt^T  — 128x128 tiles, 1024 CTAs (6.92 waves, no tail loss)
    dim3 gy(DIM/128, MTOT/128, 1);
    yproj<<<gy, 256, SM2>>>(xhi, xlo, gth, gtl, yhi, ylo);

    // 6) flash-partial scores (+ col bias w) + softmax partials + vwo dot
    dim3 gf(NQT, NKT, BATCH);
    flash_scores<<<gf, 256, SM4>>>(yhi, ylo, xhi, xlo, w, vwo, pm, ps, pd);

    // 7) combine partials -> out
    combine<<<MTOT / 256, 256>>>(pm, ps, pd, bo, out);
}

// round 10
// speedup vs baseline: 6.7767x; 1.0280x over previous
#include <cuda_runtime.h>
#include <cuda_bf16.h>
#include <cstdint>

#define BATCH 8
#define SEQ   2048
#define DIM   1024
#define MTOT  (BATCH*SEQ)              // 16384
#define NKT   8                        // k-tiles of 256 per sequence
#define NQT   16                       // q-tiles of 128 per sequence

// ===================== scratch (device globals, allocation-free) =====================
__device__ __align__(16) __nv_bfloat16 g_xhi[(size_t)MTOT*DIM];
__device__ __align__(16) __nv_bfloat16 g_xlo[(size_t)MTOT*DIM];
__device__ __align__(16) __nv_bfloat16 g_yhi[(size_t)MTOT*DIM];
__device__ __align__(16) __nv_bfloat16 g_ylo[(size_t)MTOT*DIM];
__device__ __align__(16) __nv_bfloat16 g_wqh[(size_t)DIM*DIM];
__device__ __align__(16) __nv_bfloat16 g_wql[(size_t)DIM*DIM];
__device__ __align__(16) __nv_bfloat16 g_wkh[(size_t)DIM*DIM];
__device__ __align__(16) __nv_bfloat16 g_wkl[(size_t)DIM*DIM];
__device__ __align__(16) float         g_gtpart[(size_t)4*DIM*DIM];   // split-K partials
__device__ __align__(16) __nv_bfloat16 g_gthi[(size_t)DIM*DIM];      // Gt = Wk Wq^T
__device__ __align__(16) __nv_bfloat16 g_gtlo[(size_t)DIM*DIM];
__device__ __align__(16) float         g_wvo[DIM + 1];
__device__ __align__(16) float         g_wkbq[DIM];
__device__ __align__(16) float         g_vwo[(size_t)MTOT];
__device__ __align__(16) float         g_w  [(size_t)MTOT];          // per-token score col-bias
__device__ __align__(16) float         g_pm[(size_t)BATCH*NQT*NKT*128];
__device__ __align__(16) float         g_psum[(size_t)BATCH*NQT*NKT*128];
__device__ __align__(16) float         g_pd[(size_t)BATCH*NQT*NKT*128];

// ===================== helpers =====================
__device__ __forceinline__ uint32_t smem_u32(const void* p) {
    uint32_t a;
    asm("{ .reg .u64 t; cvta.to.shared.u64 t, %1; cvt.u32.u64 %0, t; }" : "=r"(a) : "l"(p));
    return a;
}
__device__ __forceinline__ void cp16(uint32_t saddr, const void* g) {
    asm volatile("cp.async.cg.shared.global [%0], [%1], 16;" :: "r"(saddr), "l"(g));
}
__device__ __forceinline__ void cp_commit() {
    asm volatile("cp.async.commit_group;" ::: "memory");
}
__device__ __forceinline__ void ldsm4(uint32_t* r, uint32_t addr) {
    asm volatile("ldmatrix.sync.aligned.m8n8.x4.shared.b16 {%0,%1,%2,%3}, [%4];"
                 : "=r"(r[0]), "=r"(r[1]), "=r"(r[2]), "=r"(r[3]) : "r"(addr));
}
__device__ __forceinline__ void mma_bf16(float* c, const uint32_t* a, uint32_t b0, uint32_t b1) {
    asm volatile(
        "mma.sync.aligned.m16n8k16.row.col.f32.bf16.bf16.f32 "
        "{%0,%1,%2,%3},{%4,%5,%6,%7},{%8,%9},{%0,%1,%2,%3};"
        : "+f"(c[0]), "+f"(c[1]), "+f"(c[2]), "+f"(c[3])
        : "r"(a[0]), "r"(a[1]), "r"(a[2]), "r"(a[3]), "r"(b0), "r"(b1));
}
__device__ __forceinline__ void split1(float v, __nv_bfloat16& h, __nv_bfloat16& l) {
    h = __float2bfloat16(v);
    l = __float2bfloat16(v - __bfloat162float(h));
}
__device__ __forceinline__ uint32_t swz(uint32_t off) {   // SW128 swizzle
    return off ^ ((off >> 3) & 0x70);
}

// ===================== templated GEMM mainloop =====================
// Tile 128(M) x (NJ*64)(N) x 64(K-chunk). 256 threads = 8 warps.
template<int NJ>
struct ML {
    static constexpr int OFF_ALO = 16384;
    static constexpr int OFF_BHI = 32768;
    static constexpr int OFF_BLO = 32768 + NJ * 8192;
    static constexpr int STG     = 32768 + NJ * 16384;
};

template<int NJ>
__device__ __forceinline__ void prefetch_chunk(
    uint32_t sbase, const __nv_bfloat16* Ahi, const __nv_bfloat16* Alo,
    const __nv_bfloat16* Bhi, const __nv_bfloat16* Blo,
    int rowA0, int rowB0, int ku4, int ldAu4, int ldBu4, int tid)
{
    #pragma unroll
    for (int t = 0; t < 4; t++) {                 // A: 128 rows x 8 u4
        int idx = tid + t * 256;
        int r = idx >> 3, c = idx & 7;
        uint32_t soff = swz((uint32_t)(r * 128 + c * 16));
        size_t gA = (size_t)(rowA0 + r) * ldAu4 + ku4 + c;
        cp16(sbase + soff,                   (const uint4*)Ahi + gA);
        cp16(sbase + ML<NJ>::OFF_ALO + soff, (const uint4*)Alo + gA);
    }
    #pragma unroll
    for (int t = 0; t < NJ * 2; t++) {            // B: NJ*64 rows x 8 u4
        int idx = tid + t * 256;
        int r = idx >> 3, c = idx & 7;
        uint32_t soff = swz((uint32_t)(r * 128 + c * 16));
        size_t gB = (size_t)(rowB0 + r) * ldBu4 + ku4 + c;
        cp16(sbase + ML<NJ>::OFF_BHI + soff, (const uint4*)Bhi + gB);
        cp16(sbase + ML<NJ>::OFF_BLO + soff, (const uint4*)Blo + gB);
    }
}

// Single barrier per chunk; A-fragments software-pipelined across ks
// (ks+1's A ldsm issued before ks's MMA block to hide LDS latency).
template<int NJ>
__device__ __forceinline__ void gemm_mainloop(
    float (&acc)[4][2*NJ][4], uint32_t sb,
    const __nv_bfloat16* Ahi, const __nv_bfloat16* Alo,
    const __nv_bfloat16* Bhi, const __nv_bfloat16* Blo,
    int rowA0, int rowB0, int nk, int ldAu4, int ldBu4,
    int tid, int wm, int wn, int lrow, int lcolB)
{
    prefetch_chunk<NJ>(sb, Ahi, Alo, Bhi, Blo, rowA0, rowB0, 0, ldAu4, ldBu4, tid);
    cp_commit();

    for (int i = 0; i < nk; i++) {
        const uint32_t stg = sb + (uint32_t)(i & 1) * ML<NJ>::STG;
        asm volatile("cp.async.wait_group 0;" ::: "memory");
        __syncthreads();
        if (i + 1 < nk) {
            prefetch_chunk<NJ>(sb + (uint32_t)((i + 1) & 1) * ML<NJ>::STG,
                               Ahi, Alo, Bhi, Blo, rowA0, rowB0, (i + 1) << 3,
                               ldAu4, ldBu4, tid);
            cp_commit();
        }

        uint32_t ah[2][4][4], al[2][4][4];
        // preload ks=0 A fragments
        #pragma unroll
        for (int mi = 0; mi < 4; mi++) {
            uint32_t off = swz((uint32_t)((wm * 64 + mi * 16 + lrow) * 128 + lcolB));
            ldsm4(ah[0][mi], stg + off);
            ldsm4(al[0][mi], stg + ML<NJ>::OFF_ALO + off);
        }
        #pragma unroll
        for (int ks = 0; ks < 4; ks++) {
            const int cur = ks & 1, nxt = cur ^ 1;
            if (ks < 3) {   // issue ks+1 A loads before this ks's MMAs
                #pragma unroll
                for (int mi = 0; mi < 4; mi++) {
                    uint32_t off = swz((uint32_t)((wm * 64 + mi * 16 + lrow) * 128
                                                  + (ks + 1) * 32 + lcolB));
                    ldsm4(ah[nxt][mi], stg + off);
                    ldsm4(al[nxt][mi], stg + ML<NJ>::OFF_ALO + off);
                }
            }
            const int kb = ks * 32 + lcolB;
            #pragma unroll
            for (int nj = 0; nj < NJ; nj++) {
                uint32_t off = swz((uint32_t)((wn * (NJ * 16) + nj * 16 + lrow) * 128 + kb));
                uint32_t bh[4], bl[4];
                ldsm4(bh, stg + ML<NJ>::OFF_BHI + off);
                ldsm4(bl, stg + ML<NJ>::OFF_BLO + off);
                #pragma unroll
                for (int mi = 0; mi < 4; mi++) {
                    #pragma unroll
                    for (int lo = 0; lo < 2; lo++) {
                        float* a = acc[mi][nj * 2 + lo];
                        mma_bf16(a, ah[cur][mi], bh[lo], bh[lo + 2]);
                        mma_bf16(a, ah[cur][mi], bl[lo], bl[lo + 2]);
                        mma_bf16(a, al[cur][mi], bh[lo], bh[lo + 2]);
                    }
                }
            }
        }
    }
    // No trailing sync; all call sites have even nk (last chunk in stage 1),
    // so stage-0 smem is safe to reuse for epilogue scratch.
}

#define DECL_ACC(ACC, NJ2)                                                           \
    float ACC[4][NJ2][4];                                                            \
    _Pragma("unroll")                                                                \
    for (int mi = 0; mi < 4; mi++)                                                   \
        _Pragma("unroll")                                                            \
        for (int ni = 0; ni < (NJ2); ni++)                                           \
            _Pragma("unroll")                                                        \
            for (int q = 0; q < 4; q++) ACC[mi][ni][q] = 0.f;

// ===================== kernel: Gt split-K partial (NJ=4) =====================
__global__ __launch_bounds__(256, 1) void gt_partial(
    const __nv_bfloat16* __restrict__ wkh, const __nv_bfloat16* __restrict__ wkl,
    const __nv_bfloat16* __restrict__ wqh, const __nv_bfloat16* __restrict__ wql,
    float* __restrict__ part)
{
    extern __shared__ char smem[];
    const uint32_t sb = smem_u32(smem);
    const int tid  = threadIdx.x;
    const int wid  = tid >> 5;
    const int lane = tid & 31;
    const int tileM = blockIdx.y * 128;
    const int tileN = blockIdx.x * 256;
    const int kofs  = blockIdx.z * 256;
    const int wm = wid >> 2, wn = wid & 3;
    const int lrow = lane & 15, lcolB = (lane >> 4) * 16;

    DECL_ACC(acc, 8);
    gemm_mainloop<4>(acc, sb, wkh + kofs, wkl + kofs, wqh + kofs, wql + kofs,
                     tileM, tileN, 4, DIM/8, DIM/8, tid, wm, wn, lrow, lcolB);

    float* C = part + (size_t)blockIdx.z * DIM * DIM;
    const int l4 = lane >> 2;
    const int l2 = (lane & 3) * 2;
    #pragma unroll
    for (int mi = 0; mi < 4; mi++) {
        #pragma unroll
        for (int ni = 0; ni < 8; ni++) {
            const int m = tileM + wm * 64 + mi * 16 + l4;
            const int n = tileN + wn * 64 + ni * 8 + l2;
            const size_t r0 = (size_t)m * DIM + n;
            *(float2*)(C + r0)                   = make_float2(acc[mi][ni][0], acc[mi][ni][1]);
            *(float2*)(C + r0 + (size_t)8 * DIM) = make_float2(acc[mi][ni][2], acc[mi][ni][3]);
        }
    }
}

// sum 4 partials, split to bf16 hi/lo
__global__ __launch_bounds__(256) void gt_reduce_split(
    const float* __restrict__ part, __nv_bfloat16* __restrict__ hi,
    __nv_bfloat16* __restrict__ lo)
{
    const size_t i = (size_t)blockIdx.x * 256 + threadIdx.x;
    const float4* p = (const float4*)part;
    const size_t n4 = (size_t)DIM * DIM / 4;
    float v[8];
    #pragma unroll
    for (int h = 0; h < 2; h++) {
        float4 s = p[2*i + h];
        #pragma unroll
        for (int z = 1; z < 4; z++) {
            float4 a = p[z * n4 + 2*i + h];
            s.x += a.x; s.y += a.y; s.z += a.z; s.w += a.w;
        }
        v[4*h+0]=s.x; v[4*h+1]=s.y; v[4*h+2]=s.z; v[4*h+3]=s.w;
    }
    uint32_t hw[4], lw[4];
    #pragma unroll
    for (int j = 0; j < 4; j++) {
        __nv_bfloat16 h0,l0,h1,l1;
        split1(v[2*j],h0,l0); split1(v[2*j+1],h1,l1);
        hw[j] = (uint32_t)__bfloat16_as_ushort(h0) | ((uint32_t)__bfloat16_as_ushort(h1) << 16);
        lw[j] = (uint32_t)__bfloat16_as_ushort(l0) | ((uint32_t)__bfloat16_as_ushort(l1) << 16);
    }
    ((uint4*)hi)[i] = make_uint4(hw[0], hw[1], hw[2], hw[3]);
    ((uint4*)lo)[i] = make_uint4(lw[0], lw[1], lw[2], lw[3]);
}

// ===================== kernel: y projection (NJ=2, 128x128, 1024 CTAs) ==========
__global__ __launch_bounds__(256, 1) void yproj(
    const __nv_bfloat16* __restrict__ Ahi, const __nv_bfloat16* __restrict__ Alo,
    const __nv_bfloat16* __restrict__ Bhi, const __nv_bfloat16* __restrict__ Blo,
    __nv_bfloat16* __restrict__ Chi, __nv_bfloat16* __restrict__ Clo)
{
    extern __shared__ char smem[];
    const uint32_t sb = smem_u32(smem);
    const int tid  = threadIdx.x;
    const int wid  = tid >> 5;
    const int lane = tid & 31;
    const int tileM = blockIdx.y * 128;
    const int tileN = blockIdx.x * 128;
    const int wm = wid >> 2, wn = wid & 3;
    const int lrow = lane & 15, lcolB = (lane >> 4) * 16;

    DECL_ACC(acc, 4);
    gemm_mainloop<2>(acc, sb, Ahi, Alo, Bhi, Blo, tileM, tileN, DIM/64,
                     DIM/8, DIM/8, tid, wm, wn, lrow, lcolB);

    const int l4 = lane >> 2;
    const int l2 = (lane & 3) * 2;
    #pragma unroll
    for (int mi = 0; mi < 4; mi++) {
        #pragma unroll
        for (int ni = 0; ni < 4; ni++) {
            const int m = tileM + wm * 64 + mi * 16 + l4;
            const int n = tileN + wn * 32 + ni * 8 + l2;
            const size_t r0 = (size_t)m * DIM + n;
            const size_t r1 = r0 + (size_t)8 * DIM;
            __nv_bfloat16 h0,l0,h1,l1,h2,l2b,h3,l3;
            split1(acc[mi][ni][0],h0,l0); split1(acc[mi][ni][1],h1,l1);
            split1(acc[mi][ni][2],h2,l2b); split1(acc[mi][ni][3],h3,l3);
            *(uint32_t*)(Chi + r0) = (uint32_t)__bfloat16_as_ushort(h0) | ((uint32_t)__bfloat16_as_ushort(h1) << 16);
            *(uint32_t*)(Clo + r0) = (uint32_t)__bfloat16_as_ushort(l0) | ((uint32_t)__bfloat16_as_ushort(l1) << 16);
            *(uint32_t*)(Chi + r1) = (uint32_t)__bfloat16_as_ushort(h2) | ((uint32_t)__bfloat16_as_ushort(h3) << 16);
            *(uint32_t*)(Clo + r1) = (uint32_t)__bfloat16_as_ushort(l2b)| ((uint32_t)__bfloat16_as_ushort(l3) << 16);
        }
    }
}

// ===================== kernel: flash-partial scores (NJ=4) =====================
__global__ __launch_bounds__(256, 1) void flash_scores(
    const __nv_bfloat16* __restrict__ yhi, const __nv_bfloat16* __restrict__ ylo,
    const __nv_bfloat16* __restrict__ xhi, const __nv_bfloat16* __restrict__ xlo,
    const float* __restrict__ wbias, const float* __restrict__ vwo,
    float* __restrict__ pm, float* __restrict__ ps, float* __restrict__ pd)
{
    extern __shared__ char smem[];
    const uint32_t sb = smem_u32(smem);
    const int tid  = threadIdx.x;
    const int wid  = tid >> 5;
    const int lane = tid & 31;
    const int qt = blockIdx.x, ky = blockIdx.y, z = blockIdx.z;
    const int wm = wid >> 2, wn = wid & 3;
    const int lrow = lane & 15, lcolB = (lane >> 4) * 16;

    const int rowA0 = z * SEQ + qt * 128;
    const int rowB0 = z * SEQ + ky * 256;

    DECL_ACC(acc, 8);
    gemm_mainloop<4>(acc, sb, yhi, ylo, xhi, xlo, rowA0, rowB0, DIM/64,
                     DIM/8, DIM/8, tid, wm, wn, lrow, lcolB);

    const int l4 = lane >> 2;
    const int l2 = (lane & 3) * 2;

    // add per-column bias w (fp32, exact)
    const float* wb = wbias + (size_t)z * SEQ + ky * 256;
    const float* vw = vwo   + (size_t)z * SEQ + ky * 256;
    #pragma unroll
    for (int ni = 0; ni < 8; ni++) {
        const int c = wn * 64 + ni * 8 + l2;
        const float w0 = __ldg(&wb[c]), w1 = __ldg(&wb[c + 1]);
        #pragma unroll
        for (int mi = 0; mi < 4; mi++) {
            acc[mi][ni][0] += w0; acc[mi][ni][1] += w1;
            acc[mi][ni][2] += w0; acc[mi][ni][3] += w1;
        }
    }

    // stats scratch in stage-0 smem (last chunk was stage 1; nk=16 even)
    float* pmax = (float*)smem;            // [4][128]
    float* psum = (float*)(smem + 2048);
    float* pdot = (float*)(smem + 4096);
    float* nm   = (float*)(smem + 6144);

    // 1) tile row max
    #pragma unroll
    for (int mi = 0; mi < 4; mi++) {
        float m0 = -3.0e38f, m1 = -3.0e38f;
        #pragma unroll
        for (int ni = 0; ni < 8; ni++) {
            m0 = fmaxf(m0, fmaxf(acc[mi][ni][0], acc[mi][ni][1]));
            m1 = fmaxf(m1, fmaxf(acc[mi][ni][2], acc[mi][ni][3]));
        }
        #pragma unroll
        for (int o = 1; o <= 2; o <<= 1) {
            m0 = fmaxf(m0, __shfl_xor_sync(0xffffffffu, m0, o));
            m1 = fmaxf(m1, __shfl_xor_sync(0xffffffffu, m1, o));
        }
        if ((lane & 3) == 0) {
            int r0 = wm * 64 + mi * 16 + l4;
            pmax[wn * 128 + r0]     = m0;
            pmax[wn * 128 + r0 + 8] = m1;
        }
    }
    __syncthreads();
    if (tid < 128) {
        nm[tid] = fmaxf(fmaxf(pmax[tid], pmax[128 + tid]),
                        fmaxf(pmax[256 + tid], pmax[384 + tid]));
    }
    __syncthreads();

    // 2) exp sums + vwo dot
    #pragma unroll
    for (int mi = 0; mi < 4; mi++) {
        const int r0 = wm * 64 + mi * 16 + l4;
        const float m0 = nm[r0], m1 = nm[r0 + 8];
        float s0 = 0.f, d0 = 0.f, s1 = 0.f, d1 = 0.f;
        #pragma unroll
        for (int ni = 0; ni < 8; ni++) {
            const int c = wn * 64 + ni * 8 + l2;
            const float v0 = __ldg(&vw[c]), v1 = __ldg(&vw[c + 1]);
            float e;
            e = __expf(acc[mi][ni][0] - m0); s0 += e; d0 += e * v0;
            e = __expf(acc[mi][ni][1] - m0); s0 += e; d0 += e * v1;
            e = __expf(acc[mi][ni][2] - m1); s1 += e; d1 += e * v0;
            e = __expf(acc[mi][ni][3] - m1); s1 += e; d1 += e * v1;
        }
        #pragma unroll
        for (int o = 1; o <= 2; o <<= 1) {
            s0 += __shfl_xor_sync(0xffffffffu, s0, o);
            d0 += __shfl_xor_sync(0xffffffffu, d0, o);
            s1 += __shfl_xor_sync(0xffffffffu, s1, o);
            d1 += __shfl_xor_sync(0xffffffffu, d1, o);
        }
        if ((lane & 3) == 0) {
            psum[wn * 128 + r0]     = s0;  pdot[wn * 128 + r0]     = d0;
            psum[wn * 128 + r0 + 8] = s1;  pdot[wn * 128 + r0 + 8] = d1;
        }
    }
    __syncthreads();

    if (tid < 128) {
        float s = psum[tid] + psum[128 + tid] + psum[256 + tid] + psum[384 + tid];
        float d = pdot[tid] + pdot[128 + tid] + pdot[256 + tid] + pdot[384 + tid];
        size_t idx = (((size_t)z * NQT + qt) * NKT + ky) * 128 + tid;
        pm[idx] = nm[tid];
        ps[idx] = s;
        pd[idx] = d;
    }
}

// ===================== kernel: combine partials =====================
__global__ __launch_bounds__(256) void combine(
    const float* __restrict__ pm, const float* __restrict__ ps,
    const float* __restrict__ pd, const float* __restrict__ bo,
    float* __restrict__ out)
{
    const int row = blockIdx.x * 256 + threadIdx.x;
    if (row >= MTOT) return;
    const int z = row / SEQ;
    const int sr = row % SEQ;
    const int qt = sr / 128, r = sr % 128;
    const size_t base = (((size_t)z * NQT + qt) * NKT) * 128 + r;

    float M = -3.0e38f;
    #pragma unroll
    for (int k = 0; k < NKT; k++) M = fmaxf(M, pm[base + k * 128]);
    float s = 0.f, d = 0.f;
    #pragma unroll
    for (int k = 0; k < NKT; k++) {
        float c = __expf(pm[base + k * 128] - M);
        s += ps[base + k * 128] * c;
        d += pd[base + k * 128] * c;
    }
    out[row] = d / s + bo[0];
}

// ===================== small kernels (merged) =====================
// rows 0..DIM: wvo[r] = dot(Wv[r,:] or bv, Wo); rows DIM+1..2*DIM: wkbq[r-DIM-1] = dot(Wk[row,:], bq)
__global__ __launch_bounds__(256) void prep_vecs(
    const float* __restrict__ Wv, const float* __restrict__ bv,
    const float* __restrict__ Wo, const float* __restrict__ Wk,
    const float* __restrict__ bq,
    float* __restrict__ wvo, float* __restrict__ wkbq)
{
    const int row  = (blockIdx.x * blockDim.x + threadIdx.x) >> 5;
    const int lane = threadIdx.x & 31;
    if (row > 2 * DIM) return;
    const float* src;
    const float* vec;
    if (row <= DIM) {
        src = (row < DIM) ? (Wv + (size_t)row * DIM) : bv;
        vec = Wo;
    } else {
        src = Wk + (size_t)(row - DIM - 1) * DIM;
        vec = bq;
    }
    float s = 0.f;
    #pragma unroll 8
    for (int i = lane; i < DIM; i += 32) s += src[i] * vec[i];
    #pragma unroll
    for (int o = 16; o; o >>= 1) s += __shfl_xor_sync(0xffffffffu, s, o);
    if (lane == 0) {
        if (row <= DIM) wvo[row] = s;
        else            wkbq[row - DIM - 1] = s;
    }
}

// one warp per token: split x -> hi/lo AND vwo = x.wvo + bvwo AND w = x.wkbq
__global__ __launch_bounds__(256) void xprep(
    const float* __restrict__ x, const float* __restrict__ wvo,
    const float* __restrict__ wkbq,
    __nv_bfloat16* __restrict__ hi, __nv_bfloat16* __restrict__ lo,
    float* __restrict__ vwo_out, float* __restrict__ w_out)
{
    const int row  = (blockIdx.x * blockDim.x + threadIdx.x) >> 5;
    const int lane = threadIdx.x & 31;
    if (row >= MTOT) return;
    const float4* xr = (const float4*)(x + (size_t)row * DIM);
    const float4* wv = (const float4*)wvo;
    const float4* wk = (const float4*)wkbq;
    uint2* hr = (uint2*)(hi + (size_t)row * DIM);
    uint2* lr = (uint2*)(lo + (size_t)row * DIM);
    float s = 0.f, t = 0.f;
    #pragma unroll
    for (int j = 0; j < 8; j++) {
        const int i = lane + j * 32;
        float4 a = __ldg(&xr[i]);
        float4 b = __ldg(&wv[i]);
        float4 c = __ldg(&wk[i]);
        s += a.x*b.x + a.y*b.y + a.z*b.z + a.w*b.w;
        t += a.x*c.x + a.y*c.y + a.z*c.z + a.w*c.w;
        __nv_bfloat16 h0,l0,h1,l1,h2,l2,h3,l3;
        split1(a.x,h0,l0); split1(a.y,h1,l1); split1(a.z,h2,l2); split1(a.w,h3,l3);
        uint2 hw, lw;
        hw.x = (uint32_t)__bfloat16_as_ushort(h0) | ((uint32_t)__bfloat16_as_ushort(h1) << 16);
        hw.y = (uint32_t)__bfloat16_as_ushort(h2) | ((uint32_t)__bfloat16_as_ushort(h3) << 16);
        lw.x = (uint32_t)__bfloat16_as_ushort(l0) | ((uint32_t)__bfloat16_as_ushort(l1) << 16);
        lw.y = (uint32_t)__bfloat16_as_ushort(l2) | ((uint32_t)__bfloat16_as_ushort(l3) << 16);
        hr[i] = hw;  lr[i] = lw;
    }
    #pragma unroll
    for (int o = 16; o; o >>= 1) {
        s += __shfl_xor_sync(0xffffffffu, s, o);
        t += __shfl_xor_sync(0xffffffffu, t, o);
    }
    if (lane == 0) { vwo_out[row] = s + wvo[DIM]; w_out[row] = t; }
}

// both weight splits in one kernel: blockIdx.y = 0 -> Wq, 1 -> Wk
__global__ __launch_bounds__(256) void split_weights(
    const float* __restrict__ Wq, const float* __restrict__ Wk,
    __nv_bfloat16* __restrict__ wqh, __nv_bfloat16* __restrict__ wql,
    __nv_bfloat16* __restrict__ wkh, __nv_bfloat16* __restrict__ wkl)
{
    const float* in = blockIdx.y ? Wk : Wq;
    __nv_bfloat16* hi = blockIdx.y ? wkh : wqh;
    __nv_bfloat16* lo = blockIdx.y ? wkl : wql;
    const int i = blockIdx.x * 256 + threadIdx.x;   // uint4 index, DIM*DIM/8 total
    const float4* p = (const float4*)in;
    float4 a = p[2*i], b = p[2*i+1];
    float vv[8] = {a.x, a.y, a.z, a.w, b.x, b.y, b.z, b.w};
    uint32_t hw[4], lw[4];
    #pragma unroll
    for (int j = 0; j < 4; j++) {
        __nv_bfloat16 h0, l0, h1, l1;
        split1(vv[2*j],   h0, l0);
        split1(vv[2*j+1], h1, l1);
        hw[j] = (uint32_t)__bfloat16_as_ushort(h0) | ((uint32_t)__bfloat16_as_ushort(h1) << 16);
        lw[j] = (uint32_t)__bfloat16_as_ushort(l0) | ((uint32_t)__bfloat16_as_ushort(l1) << 16);
    }
    ((uint4*)hi)[i] = make_uint4(hw[0], hw[1], hw[2], hw[3]);
    ((uint4*)lo)[i] = make_uint4(lw[0], lw[1], lw[2], lw[3]);
}

// ===================== launch =====================
extern "C" void kernel_launch(void* const* d_in, const int* in_sizes, int n_in,
                              void* d_out, int out_size)
{
    const float* x  = (const float*)d_in[0];
    const float* Wq = (const float*)d_in[1];
    const float* bq = (const float*)d_in[2];
    const float* Wk = (const float*)d_in[3];
    const float* bk = (const float*)d_in[4];
    const float* Wv = (const float*)d_in[5];
    const float* bv = (const float*)d_in[6];
    const float* Wo = (const float*)d_in[7];
    const float* bo = (const float*)d_in[8];
    float* out = (float*)d_out;
    (void)bk;   // cancels in softmax (row-constant)

    __nv_bfloat16 *xhi,*xlo,*yhi,*ylo,*wqh,*wql,*wkh,*wkl,*gth,*gtl;
    float *gtpart,*wvo,*wkbq,*vwo,*w,*pm,*ps,*pd;
    cudaGetSymbolAddress((void**)&xhi, g_xhi);  cudaGetSymbolAddress((void**)&xlo, g_xlo);
    cudaGetSymbolAddress((void**)&yhi, g_yhi);  cudaGetSymbolAddress((void**)&ylo, g_ylo);
    cudaGetSymbolAddress((void**)&wqh, g_wqh);  cudaGetSymbolAddress((void**)&wql, g_wql);
    cudaGetSymbolAddress((void**)&wkh, g_wkh);  cudaGetSymbolAddress((void**)&wkl, g_wkl);
    cudaGetSymbolAddress((void**)&gth, g_gthi); cudaGetSymbolAddress((void**)&gtl, g_gtlo);
    cudaGetSymbolAddress((void**)&gtpart, g_gtpart);
    cudaGetSymbolAddress((void**)&wvo, g_wvo);  cudaGetSymbolAddress((void**)&wkbq, g_wkbq);
    cudaGetSymbolAddress((void**)&vwo, g_vwo);  cudaGetSymbolAddress((void**)&w,   g_w);
    cudaGetSymbolAddress((void**)&pm,  g_pm);
    cudaGetSymbolAddress((void**)&ps,  g_psum); cudaGetSymbolAddress((void**)&pd,  g_pd);

    const int SM4 = 2 * ML<4>::STG;   // 196608
    const int SM2 = 2 * ML<2>::STG;   // 131072
    cudaFuncSetAttribute(gt_partial,   cudaFuncAttributeMaxDynamicSharedMemorySize, SM4);
    cudaFuncSetAttribute(yproj,        cudaFuncAttributeMaxDynamicSharedMemorySize, SM2);
    cudaFuncSetAttribute(flash_scores, cudaFuncAttributeMaxDynamicSharedMemorySize, SM4);

    // 1) wvo + wkbq in one kernel (2049 warp-rows)
    prep_vecs<<<(2 * DIM + 1 + 7) / 8, 256>>>(Wv, bv, Wo, Wk, bq, wvo, wkbq);

    // 2) x -> hi/lo + vwo + w (one pass over x)
    xprep<<<MTOT / 8, 256>>>(x, wvo, wkbq, xhi, xlo, vwo, w);

    // 3) Wq + Wk -> hi/lo bf16 (one kernel)
    dim3 gw(DIM * DIM / 8 / 256, 2);
    split_weights<<<gw, 256>>>(Wq, Wk, wqh, wql, wkh, wkl);

    // 4) Gt = Wk @ Wq^T  (split-K x3 HMMA -> fp32 partials -> reduce+split)
    dim3 gg(DIM/256, DIM/128, 4);
    gt_partial<<<gg, 256, SM4>>>(wkh, wkl, wqh, wql, gtpart);
    gt_reduce_split<<<DIM*DIM/8/256, 256>>>(gtpart, gth, gtl);

    // 5) y = x @ Gt^T  — launch #6 (ncu profile window)
    dim3 gy(DIM/128, MTOT/128, 1);
    yproj<<<gy, 256, SM2>>>(xhi, xlo, gth, gtl, yhi, ylo);

    // 6) flash-partial scores (+ col bias w) + softmax partials + vwo dot
    dim3 gf(NQT, NKT, BATCH);
    flash_scores<<<gf, 256, SM4>>>(yhi, ylo, xhi, xlo, w, vwo, pm, ps, pd);

    // 7) combine partials -> out
    combine<<<MTOT / 256, 256>>>(pm, ps, pd, bo, out);
}